// round 4
// baseline (speedup 1.0000x reference)
#include <cuda_runtime.h>

// Problem constants
#define NN 4096   // nodes
#define DD 256    // input dim
#define HH 256    // hidden dim
#define SS 128    // sequence length
#define GRID 148
#define TPB 512
#define RPB 28    // rows per block (ceil 4096/148)
#define HROWS 14  // rows per thread-half

// Persistent device scratch
__device__ float d_hidden[NN * HH];
__device__ float d_cell[NN * HH];
__device__ float d_HW[NN * HH];      // hidden @ Wn, incrementally maintained
__device__ float d_WnT[HH * HH];     // Wn transposed: WnT[h][k] = Wn[k][h]
__device__ float d_WgT[HH * HH];     // bottom half of Wg transposed: WgT[h][k] = Wg[256+k][h]
__device__ float d_FS[SS * HH];      // inputs[seq[t]] @ Ws + bs
__device__ float d_GI[SS * HH];      // inputs[seq[t]] @ Wg[:256] + bg
__device__ float d_S1[SS * HH];      // nei_row @ hidden accumulator
__device__ float d_S2[SS * HH];      // nei_row @ sigmoid(fs + HW) accumulator
__device__ float d_curHid[HH];       // latest step's new hidden row
__device__ unsigned d_bar[512];      // monotonic grid-barrier counters

// Fast grid barrier: release-RED arrival + acquire-load spin (CG pattern, no MEMBAR.GPU)
__device__ __forceinline__ void grid_barrier(int idx) {
    __syncthreads();
    if (threadIdx.x == 0) {
        unsigned* p = &d_bar[idx];
        asm volatile("red.release.gpu.global.add.u32 [%0], 1;" :: "l"(p) : "memory");
        unsigned v;
        do {
            asm volatile("ld.acquire.gpu.global.u32 %0, [%1];" : "=r"(v) : "l"(p) : "memory");
        } while (v < GRID);
    }
    __syncthreads();
}

// MUFU sigmoid: EX2 + RCP, rel err ~1e-7
__device__ __forceinline__ float sigf(float x) {
    return __fdividef(1.0f, 1.0f + __expf(-x));
}

__global__ void lstm_init_kernel() {
    int stride = gridDim.x * blockDim.x;
    int e0 = blockIdx.x * blockDim.x + threadIdx.x;
    for (int e = e0; e < 512; e += stride) d_bar[e] = 0u;
    for (int e = e0; e < SS * HH; e += stride) { d_S1[e] = 0.0f; d_S2[e] = 0.0f; }
}

__global__ void __launch_bounds__(TPB) lstm_main_kernel(
    const float* __restrict__ inputs,   // [N, D]
    const float* __restrict__ nei,      // [N, N]
    const float* __restrict__ numNei,   // [N]
    const int*   __restrict__ seq,      // [S]
    const float* __restrict__ h0,       // [N, H]
    const float* __restrict__ c0,       // [N, H]
    const float* __restrict__ Wg,       // [D+H, H]
    const float* __restrict__ bg,       // [H]
    const float* __restrict__ Ws,       // [D, H]
    const float* __restrict__ bs,       // [H]
    const float* __restrict__ Wn,       // [H, H]
    float*       __restrict__ out)      // [N, H]
{
    const int tid = threadIdx.x;
    const int b   = blockIdx.x;
    __shared__ float sh[RPB * 256];     // 28KB, multi-purpose
    float* shw  = sh;                    // [28]  nei weights for this block's rows
    float* shs1 = sh + 32;               // [256] half-1 partial S1
    float* shs2 = sh + 288;              // [256] half-1 partial S2

    const int r0  = b * RPB;
    const int cnt = (r0 < NN) ? min(RPB, NN - r0) : 0;

    // ---------- Prologue 0a: copy state + build transposed weights ----------
    for (int e = b * TPB + tid; e < NN * HH; e += GRID * TPB) {
        d_hidden[e] = h0[e];
        d_cell[e]   = c0[e];
    }
    for (int e = b * TPB + tid; e < HH * HH; e += GRID * TPB) {
        int k = e >> 8, h = e & 255;
        d_WnT[h * 256 + k] = Wn[e];
        d_WgT[h * 256 + k] = Wg[(256 + k) * 256 + h];
    }

    // ---------- Prologue 0b: HW0 = h0 @ Wn (this block's row slice) ----------
    for (int e = tid; e < cnt * 256; e += TPB) sh[e] = h0[(size_t)r0 * 256 + e];
    __syncthreads();
    {
        const int h    = tid & 255;
        const int half = tid >> 8;
        const int base = half * HROWS;
        float acc[HROWS];
        #pragma unroll
        for (int r = 0; r < HROWS; ++r) acc[r] = 0.0f;
        for (int k = 0; k < 256; ++k) {
            float wn = __ldg(&Wn[k * 256 + h]);
            #pragma unroll
            for (int r = 0; r < HROWS; ++r)
                acc[r] = fmaf(sh[(base + r) * 256 + k], wn, acc[r]);
        }
        #pragma unroll
        for (int r = 0; r < HROWS; ++r)
            if (base + r < cnt)
                d_HW[(size_t)(r0 + base + r) * 256 + h] = acc[r];
    }
    __syncthreads();

    // ---------- Prologue 0c: FS[t] / GI[t] precompute (block t) ----------
    if (b < SS) {
        int ii = __ldg(&seq[b]);
        for (int k = tid; k < 256; k += TPB) sh[k] = inputs[(size_t)ii * 256 + k];
        __syncthreads();
        if (tid < 256) {
            const int h = tid;
            float fs = bs[h], gi = bg[h];
            for (int k = 0; k < 256; ++k) {
                float iv = sh[k];
                fs = fmaf(iv, __ldg(&Ws[k * 256 + h]), fs);
                gi = fmaf(iv, __ldg(&Wg[k * 256 + h]), gi);
            }
            d_FS[b * 256 + h] = fs;
            d_GI[b * 256 + h] = gi;
        }
    }

    grid_barrier(0);
    int barIdx = 1;

    const int lane  = tid & 31;
    const int wid   = tid >> 5;
    const int h2    = b + 148 * wid;            // owner h: wid0 -> [0,147], wid1 -> [148,255]
    const bool owner = (wid < 2) && (h2 < 256);
    const int hh    = tid & 255;
    const int half  = tid >> 8;
    const int base  = half * HROWS;
    const int cnth  = max(0, min(cnt - base, HROWS));

    // ---------- Main sequential loop: 2 grid barriers per step ----------
    for (int t = 0; t < SS; ++t) {
        const int i    = __ldg(&seq[t]);
        const int prev = (t > 0) ? __ldg(&seq[t - 1]) : -1;
        const size_t tH = (size_t)t * 256;

        // Phase A(a): owners flush step t-1's row update (HW[prev], hidden[prev])
        // and inject row prev's contribution into S1/S2 of step t.
        if (owner && prev >= 0) {
            const float4* ch4 = (const float4*)d_curHid;
            const float4* wn4 = (const float4*)(d_WnT + h2 * 256);
            float dot = 0.0f;
            #pragma unroll
            for (int q = 0; q < 2; ++q) {
                float4 a = __ldcg(&ch4[lane + 32 * q]);
                float4 w = __ldg(&wn4[lane + 32 * q]);
                dot += a.x * w.x + a.y * w.y + a.z * w.z + a.w * w.w;
            }
            #pragma unroll
            for (int o = 16; o; o >>= 1) dot += __shfl_down_sync(0xffffffffu, dot, o);
            if (lane == 0) {
                float ch = __ldcg(&d_curHid[h2]);
                d_HW[(size_t)prev * 256 + h2]     = dot;
                d_hidden[(size_t)prev * 256 + h2] = ch;
                float w   = __ldg(&nei[(size_t)i * NN + prev]);
                float fsv = __ldg(&d_FS[tH + h2]);
                atomicAdd(&d_S1[tH + h2], w * ch);
                atomicAdd(&d_S2[tH + h2], w * sigf(fsv + dot));
            }
        }

        // Phase A(b): stage nei weights, stream this block's row slice (skip prev)
        if (tid < cnt) shw[tid] = __ldg(&nei[(size_t)i * NN + r0 + tid]);
        __syncthreads();
        {
            float fsv = __ldg(&d_FS[tH + hh]);
            float s1 = 0.0f, s2 = 0.0f;
            const float* hp = d_hidden + (size_t)(r0 + base) * 256 + hh;
            const float* wp = d_HW     + (size_t)(r0 + base) * 256 + hh;
            #pragma unroll
            for (int rr = 0; rr < HROWS; ++rr) {
                if (rr < cnth && (r0 + base + rr) != prev) {
                    float w = shw[base + rr];
                    s1 = fmaf(w, __ldcg(hp + rr * 256), s1);
                    s2 = fmaf(w, sigf(fsv + __ldcg(wp + rr * 256)), s2);
                }
            }
            if (half == 1) { shs1[hh] = s1; shs2[hh] = s2; }
            __syncthreads();
            if (half == 0 && cnt > 0) {
                atomicAdd(&d_S1[tH + hh], s1 + shs1[hh]);
                atomicAdd(&d_S2[tH + hh], s2 + shs2[hh]);
            }
        }
        grid_barrier(barIdx++);

        // Phase B: distributed per-h serial update -> cell[i], curHid
        if (owner) {
            const float4* s14 = (const float4*)(d_S1 + tH);
            const float4* hi4 = (const float4*)(d_hidden + (size_t)i * 256);
            const float4* wn4 = (const float4*)(d_WnT + h2 * 256);
            const float4* wg4 = (const float4*)(d_WgT + h2 * 256);
            float dotS = 0.0f, dotG = 0.0f;
            #pragma unroll
            for (int q = 0; q < 2; ++q) {
                float4 a  = __ldcg(&s14[lane + 32 * q]);
                float4 wA = __ldg(&wn4[lane + 32 * q]);
                float4 hl = __ldcg(&hi4[lane + 32 * q]);
                float4 wB = __ldg(&wg4[lane + 32 * q]);
                dotS += a.x * wA.x + a.y * wA.y + a.z * wA.z + a.w * wA.w;
                dotG += hl.x * wB.x + hl.y * wB.y + hl.z * wB.z + hl.w * wB.w;
            }
            #pragma unroll
            for (int o = 16; o; o >>= 1) {
                dotS += __shfl_down_sync(0xffffffffu, dotS, o);
                dotG += __shfl_down_sync(0xffffffffu, dotG, o);
            }
            if (lane == 0) {
                float inv_n = 1.0f / __ldg(&numNei[i]);
                float pre   = __ldg(&d_GI[tH + h2]) + inv_n * dotS + dotG;
                float iS    = sigf(pre);
                float hC    = tanhf(pre);
                float fsv   = __ldg(&d_FS[tH + h2]);
                float fS    = sigf(fsv + __ldcg(&d_HW[(size_t)i * 256 + h2]));
                float c     = __ldcg(&d_cell[(size_t)i * 256 + h2]);
                float s2v   = __ldcg(&d_S2[tH + h2]);
                float cC    = fmaf(s2v * inv_n, c, fmaf(fS, c, iS * hC));
                d_cell[(size_t)i * 256 + h2] = cC;
                d_curHid[h2] = tanhf(iS * cC);
            }
        }
        grid_barrier(barIdx++);
    }

    // ---------- Epilogue: out = hidden + h0 (row i_last still pending in curHid) ----------
    const int ilast = __ldg(&seq[SS - 1]);
    for (int e = b * TPB + tid; e < NN * HH; e += GRID * TPB) {
        int row = e >> 8;
        float hv = (row == ilast) ? __ldcg(&d_curHid[e & 255]) : __ldcg(&d_hidden[e]);
        out[e] = hv + h0[e];
    }
}

extern "C" void kernel_launch(void* const* d_in, const int* in_sizes, int n_in,
                              void* d_out, int out_size) {
    const float* inputs  = (const float*)d_in[0];
    const float* nei     = (const float*)d_in[1];
    const float* numNei  = (const float*)d_in[2];
    const int*   seq     = (const int*)  d_in[3];
    const float* h0      = (const float*)d_in[4];
    const float* c0      = (const float*)d_in[5];
    const float* Wg      = (const float*)d_in[6];
    const float* bg      = (const float*)d_in[7];
    const float* Ws      = (const float*)d_in[8];
    const float* bs      = (const float*)d_in[9];
    const float* Wn      = (const float*)d_in[10];
    float* out = (float*)d_out;

    lstm_init_kernel<<<64, 256>>>();
    lstm_main_kernel<<<GRID, TPB>>>(inputs, nei, numNei, seq, h0, c0,
                                    Wg, bg, Ws, bs, Wn, out);
}

// round 5
// speedup vs baseline: 1.1718x; 1.1718x over previous
#include <cuda_runtime.h>

#define NN 4096
#define HH 256
#define SS 128
#define G3 32        // main-loop grid: 32 blocks x 8 warps = 256 warps = one per h
#define PRE1_GRID 148
#define RPB1 28      // rows per block in HW0/HG0 GEMM

// ---------------- persistent device scratch ----------------
__device__ __align__(16) float d_HW0[NN*HH];     // h0 @ Wn
__device__ __align__(16) float d_HG0[NN*HH];     // h0 @ Wg_bot
__device__ __align__(16) float d_FS[SS*HH];      // inp_t @ Ws + bs
__device__ __align__(16) float d_GI[SS*HH];      // inp_t @ Wg_top + bg
__device__ __align__(16) float d_NW0[SS*HH];     // (nei_t @ h0) @ Wn
__device__ __align__(16) float d_S2base[SS*HH];  // sum_j w_tj * sig(fs_t + HW0[j])
__device__ __align__(16) float d_corr1[SS*HH];   // scattered linear corrections
__device__ __align__(16) float d_corr2[SS*HH];   // scattered sigmoid corrections
__device__ __align__(16) float d_hidver[SS*HH];  // curHidden of step t
__device__ __align__(16) float d_HWver[SS*HH];   // hid_t @ Wn   (written at step t+1)
__device__ __align__(16) float d_HGver[SS*HH];   // hid_t @ Wg_bot
__device__ __align__(16) float d_HWbef[SS*HH];   // HW row of node seq[t] BEFORE step t
__device__ __align__(16) float d_cell[NN*HH];    // current cell state
__device__ int d_lastVisit[SS];                  // last u<t with seq[u]==seq[t], else -1
__device__ int d_lastStep[NN];                   // last step visiting node, else -1
__device__ unsigned d_bar[256];

// grid barrier: release-RED arrival + acquire-load spin (CG pattern)
__device__ __forceinline__ void grid_barrier(int idx) {
    __syncthreads();
    if (threadIdx.x == 0) {
        unsigned* p = &d_bar[idx];
        asm volatile("red.release.gpu.global.add.u32 [%0], 1;" :: "l"(p) : "memory");
        unsigned v;
        do {
            asm volatile("ld.acquire.gpu.global.u32 %0, [%1];" : "=r"(v) : "l"(p) : "memory");
        } while (v < G3);
    }
    __syncthreads();
}

// telescoping sigmoid: 1 MUFU (tanh.approx). MUST be used consistently for all
// S2base / correction terms so differences cancel exactly.
__device__ __forceinline__ float sig_t(float x) {
    float t;
    asm("tanh.approx.f32 %0, %1;" : "=f"(t) : "f"(0.5f * x));
    return fmaf(0.5f, t, 0.5f);
}
// accurate sigmoid for own-step gates (EX2+RCP, rel ~1e-7)
__device__ __forceinline__ float sig_e(float x) {
    return __fdividef(1.0f, 1.0f + __expf(-x));
}

__global__ void k_init() {
    int st = gridDim.x * blockDim.x, e0 = blockIdx.x * blockDim.x + threadIdx.x;
    for (int e = e0; e < 256; e += st) d_bar[e] = 0u;
    for (int e = e0; e < SS*HH; e += st) {
        d_corr1[e] = 0.f; d_corr2[e] = 0.f; d_NW0[e] = 0.f; d_S2base[e] = 0.f;
    }
    for (int e = e0; e < NN; e += st) d_lastStep[e] = -1;
}

__global__ void __launch_bounds__(256) k_pre1(
    const float* __restrict__ inputs, const int* __restrict__ seq,
    const float* __restrict__ h0, const float* __restrict__ c0,
    const float* __restrict__ Wg, const float* __restrict__ bg,
    const float* __restrict__ Ws, const float* __restrict__ bs,
    const float* __restrict__ Wn)
{
    const int tid = threadIdx.x, b = blockIdx.x;
    __shared__ float sh[RPB1 * 256];

    for (int e = b*256 + tid; e < NN*HH; e += PRE1_GRID*256) d_cell[e] = c0[e];

    int r0 = b * RPB1;
    int cnt = (r0 < NN) ? min(RPB1, NN - r0) : 0;
    for (int e = tid; e < cnt*256; e += 256) sh[e] = h0[(size_t)r0*256 + e];
    __syncthreads();
    if (cnt > 0) {
        const int h = tid;
        float acc[RPB1];
        #pragma unroll
        for (int r = 0; r < RPB1; ++r) acc[r] = 0.f;
        for (int k = 0; k < 256; ++k) {
            float wv = __ldg(&Wn[k*256 + h]);
            #pragma unroll
            for (int r = 0; r < RPB1; ++r) acc[r] = fmaf(sh[r*256 + k], wv, acc[r]);
        }
        for (int r = 0; r < cnt; ++r) d_HW0[(size_t)(r0+r)*256 + h] = acc[r];
        #pragma unroll
        for (int r = 0; r < RPB1; ++r) acc[r] = 0.f;
        for (int k = 0; k < 256; ++k) {
            float wv = __ldg(&Wg[(256 + k)*256 + h]);
            #pragma unroll
            for (int r = 0; r < RPB1; ++r) acc[r] = fmaf(sh[r*256 + k], wv, acc[r]);
        }
        for (int r = 0; r < cnt; ++r) d_HG0[(size_t)(r0+r)*256 + h] = acc[r];
    }
    __syncthreads();

    if (b < SS) {
        int ii = __ldg(&seq[b]);
        for (int k = tid; k < 256; k += 256) sh[k] = inputs[(size_t)ii*256 + k];
        __syncthreads();
        const int h = tid;
        float fs = bs[h], gi = bg[h];
        for (int k = 0; k < 256; ++k) {
            float iv = sh[k];
            fs = fmaf(iv, __ldg(&Ws[k*256 + h]), fs);
            gi = fmaf(iv, __ldg(&Wg[k*256 + h]), gi);
        }
        d_FS[b*256 + h] = fs;
        d_GI[b*256 + h] = gi;
    }

    if (b == 0 && tid < SS) {
        int me = __ldg(&seq[tid]);
        int lv = -1;
        for (int u = tid - 1; u >= 0; --u)
            if (__ldg(&seq[u]) == me) { lv = u; break; }
        d_lastVisit[tid] = lv;
        atomicMax(&d_lastStep[me], tid);
    }
}

// S2base / NW0: grid (SS/4, NN/512); block does 4 t's x 512 j's for all 256 h
__global__ void __launch_bounds__(256) k_pre2(const float* __restrict__ nei,
                                              const int* __restrict__ seq)
{
    const int tid = threadIdx.x;
    const int tt0 = blockIdx.x * 4, j0 = blockIdx.y * 512;
    __shared__ float shw[4][512];
    int sqs[4];
    #pragma unroll
    for (int q = 0; q < 4; ++q) sqs[q] = __ldg(&seq[tt0 + q]);
    for (int e = tid; e < 4*512; e += 256) {
        int q = e >> 9, j = e & 511;
        shw[q][j] = __ldg(&nei[(size_t)sqs[q]*NN + j0 + j]);
    }
    __syncthreads();
    const int h = tid;
    float fs[4], s1[4], s2[4];
    #pragma unroll
    for (int q = 0; q < 4; ++q) {
        fs[q] = __ldg(&d_FS[(tt0+q)*256 + h]); s1[q] = 0.f; s2[q] = 0.f;
    }
    for (int j = 0; j < 512; ++j) {
        float hw = __ldg(&d_HW0[(size_t)(j0+j)*256 + h]);
        #pragma unroll
        for (int q = 0; q < 4; ++q) {
            float w = shw[q][j];
            s1[q] = fmaf(w, hw, s1[q]);
            s2[q] = fmaf(w, sig_t(fs[q] + hw), s2[q]);
        }
    }
    #pragma unroll
    for (int q = 0; q < 4; ++q) {
        atomicAdd(&d_NW0[(tt0+q)*256 + h], s1[q]);
        atomicAdd(&d_S2base[(tt0+q)*256 + h], s2[q]);
    }
}

__global__ void __launch_bounds__(256) k_main(
    const float* __restrict__ nei, const float* __restrict__ numNei,
    const int* __restrict__ seq, const float* __restrict__ Wg,
    const float* __restrict__ Wn)
{
    const int tid = threadIdx.x, b = blockIdx.x;
    const int w = tid >> 5, lane = tid & 31;
    const int h = b * 8 + w;                      // this warp's owned h-column
    __shared__ __align__(16) float shWn[8][256];  // WnT[h][k]
    __shared__ __align__(16) float shWg[8][256];  // WgBotT[h][k]
    __shared__ int sseq[SS], slv[SS];

    for (int k = lane; k < 256; k += 32) {
        shWn[w][k] = __ldg(&Wn[k*256 + h]);
        shWg[w][k] = __ldg(&Wg[(256 + k)*256 + h]);
    }
    for (int e = tid; e < SS; e += 256) { sseq[e] = __ldg(&seq[e]); slv[e] = d_lastVisit[e]; }
    __syncthreads();

    for (int t = 0; t < SS; ++t) {
        const int i     = sseq[t];
        const int prev  = (t > 0) ? sseq[t-1] : -1;
        const int pprev = (t > 1) ? sseq[t-2] : -1;
        const int lv    = slv[t];
        float hwnew = 0.f, hgnew = 0.f;

        // --- W1: finalize step t-1's row: HWver/HGver[t-1] = hidver[t-1] @ {Wn, Wg_bot}
        if (t > 0) {
            const float4* hv4 = (const float4*)(d_hidver + (t-1)*256);
            const float4* a4  = (const float4*)shWn[w];
            const float4* g4  = (const float4*)shWg[w];
            #pragma unroll
            for (int q = 0; q < 2; ++q) {
                float4 x  = __ldcg(&hv4[lane + 32*q]);
                float4 wa = a4[lane + 32*q];
                float4 wgv= g4[lane + 32*q];
                hwnew += x.x*wa.x + x.y*wa.y + x.z*wa.z + x.w*wa.w;
                hgnew += x.x*wgv.x + x.y*wgv.y + x.z*wgv.z + x.w*wgv.w;
            }
            #pragma unroll
            for (int o = 16; o; o >>= 1) {
                hwnew += __shfl_xor_sync(0xffffffffu, hwnew, o);
                hgnew += __shfl_xor_sync(0xffffffffu, hgnew, o);
            }
            if (lane == 0) {
                d_HWver[(t-1)*256 + h] = hwnew;
                d_HGver[(t-1)*256 + h] = hgnew;
            }
        }

        // --- W2: per-h elementwise update for step t (lane 0 of each warp)
        if (lane == 0) {
            const int tb = t*256 + h;
            float fsv = __ldg(&d_FS[tb]);
            float S1 = __ldg(&d_NW0[tb])    + __ldcg(&d_corr1[tb]);
            float S2 = __ldg(&d_S2base[tb]) + __ldcg(&d_corr2[tb]);
            if (t > 0) {   // fresh correction: visit t-1
                float w1 = __ldg(&nei[(size_t)i*NN + prev]);
                float hb = __ldcg(&d_HWbef[(t-1)*256 + h]);
                S1 = fmaf(w1, hwnew - hb, S1);
                S2 = fmaf(w1, sig_t(fsv + hwnew) - sig_t(fsv + hb), S2);
            }
            if (t > 1) {   // fresh correction: visit t-2
                float w2  = __ldg(&nei[(size_t)i*NN + pprev]);
                float hv2 = __ldcg(&d_HWver[(t-2)*256 + h]);
                float hb2 = __ldcg(&d_HWbef[(t-2)*256 + h]);
                S1 = fmaf(w2, hv2 - hb2, S1);
                S2 = fmaf(w2, sig_t(fsv + hv2) - sig_t(fsv + hb2), S2);
            }
            float HWi, HGi;
            if (lv == t-1 && t > 0)      { HWi = hwnew; HGi = hgnew; }
            else if (lv >= 0)            { HWi = __ldcg(&d_HWver[lv*256 + h]);
                                           HGi = __ldcg(&d_HGver[lv*256 + h]); }
            else                         { HWi = __ldg(&d_HW0[(size_t)i*256 + h]);
                                           HGi = __ldg(&d_HG0[(size_t)i*256 + h]); }
            float inv_n = __fdividef(1.0f, __ldg(&numNei[i]));
            float pre = __ldg(&d_GI[tb]) + HGi + S1 * inv_n;
            float iS  = sig_e(pre);
            float hC  = fmaf(2.f, sig_e(2.f*pre), -1.f);    // tanh(pre)
            float fS  = sig_e(fsv + HWi);
            float c   = __ldcg(&d_cell[(size_t)i*256 + h]);
            float cC  = fmaf(S2*inv_n, c, fmaf(fS, c, iS*hC));
            d_cell[(size_t)i*256 + h] = cC;
            float xx = iS * cC;
            d_hidver[tb] = fmaf(2.f, sig_e(2.f*xx), -1.f);  // tanh
            d_HWbef[tb]  = HWi;
        }

        // --- W3: scatter visit u = t-2 into steps t' >= t+1 (all threads)
        if (t > 1) {
            const int cntS = (SS - 1 - t) * 256;
            const int base2 = (t-2)*256;
            for (int e = b*256 + tid; e < cntS; e += G3*256) {
                int tp = t + 1 + (e >> 8), hp = e & 255;
                float hv = __ldcg(&d_HWver[base2 + hp]);
                float hb = __ldcg(&d_HWbef[base2 + hp]);
                float wp = __ldg(&nei[(size_t)sseq[tp]*NN + pprev]);
                float fsp = __ldg(&d_FS[tp*256 + hp]);
                int idx = tp*256 + hp;
                d_corr1[idx] = __ldcg(&d_corr1[idx]) + wp * (hv - hb);
                d_corr2[idx] = __ldcg(&d_corr2[idx]) + wp * (sig_t(fsp + hv) - sig_t(fsp + hb));
            }
        }
        grid_barrier(t);
    }
}

__global__ void __launch_bounds__(256) k_epi(const float* __restrict__ h0,
                                             float* __restrict__ out)
{
    for (int e = blockIdx.x*blockDim.x + threadIdx.x; e < NN*HH;
         e += gridDim.x*blockDim.x) {
        int node = e >> 8;
        int ls = __ldg(&d_lastStep[node]);
        float hval = (ls >= 0) ? d_hidver[ls*256 + (e & 255)] : __ldg(&h0[e]);
        out[e] = hval + __ldg(&h0[e]);
    }
}

extern "C" void kernel_launch(void* const* d_in, const int* in_sizes, int n_in,
                              void* d_out, int out_size) {
    const float* inputs  = (const float*)d_in[0];
    const float* nei     = (const float*)d_in[1];
    const float* numNei  = (const float*)d_in[2];
    const int*   seq     = (const int*)  d_in[3];
    const float* h0      = (const float*)d_in[4];
    const float* c0      = (const float*)d_in[5];
    const float* Wg      = (const float*)d_in[6];
    const float* bg      = (const float*)d_in[7];
    const float* Ws      = (const float*)d_in[8];
    const float* bs      = (const float*)d_in[9];
    const float* Wn      = (const float*)d_in[10];
    float* out = (float*)d_out;

    k_init<<<64, 256>>>();
    k_pre1<<<PRE1_GRID, 256>>>(inputs, seq, h0, c0, Wg, bg, Ws, bs, Wn);
    k_pre2<<<dim3(SS/4, NN/512), 256>>>(nei, seq);
    k_main<<<G3, 256>>>(nei, numNei, seq, Wg, Wn);
    k_epi<<<148, 256>>>(h0, out);
}

// round 6
// speedup vs baseline: 1.1868x; 1.0128x over previous
#include <cuda_runtime.h>

#define NN 4096
#define HH 256
#define SS 128
#define PRE1_GRID 148
#define RPB1 28

#define CTAS 8          // one cluster of 8 CTAs
#define MTPB 1024       // 32 warps per CTA, 1 warp per owned h-column
#define HPC 32          // h-columns per CTA

// ---------------- persistent device scratch ----------------
__device__ __align__(16) float d_HW0[NN*HH];     // h0 @ Wn
__device__ __align__(16) float d_HG0[NN*HH];     // h0 @ Wg_bot
__device__ __align__(16) float d_FS[SS*HH];      // inp_t @ Ws + bs
__device__ __align__(16) float d_GI[SS*HH];      // inp_t @ Wg_top + bg
__device__ __align__(16) float d_NW0[SS*HH];     // (nei_t @ h0) @ Wn
__device__ __align__(16) float d_S2base[SS*HH];  // sum_j w_tj * sig(fs_t + HW0[j])
__device__ __align__(16) float d_corr1[SS*HH];   // scattered linear corrections
__device__ __align__(16) float d_corr2[SS*HH];   // scattered sigmoid corrections
__device__ __align__(16) float d_hidver[SS*HH];  // curHidden of step t
__device__ __align__(16) float d_HWver[SS*HH];   // hid_t @ Wn (finalized at step t+1)
__device__ __align__(16) float d_HWbef[SS*HH];   // HW row of seq[t] BEFORE step t
__device__ __align__(16) float d_cell[NN*HH];
__device__ __align__(16) float d_pairW[SS*SS];   // pairW[u*SS+t'] = nei[seq[t']][seq[u]]
__device__ float d_invN[SS];                     // 1 / numNei[seq[t]]
__device__ int   d_lastVisit[SS];                // last u<t with seq[u]==seq[t], else -1
__device__ int   d_lastStep[NN];                 // last step visiting node, else -1

// telescoping sigmoid: 1 MUFU (tanh.approx). Must be used consistently so
// S2base / correction differences cancel exactly.
__device__ __forceinline__ float sig_t(float x) {
    float t;
    asm("tanh.approx.f32 %0, %1;" : "=f"(t) : "f"(0.5f * x));
    return fmaf(0.5f, t, 0.5f);
}
// accurate sigmoid for own-step gates
__device__ __forceinline__ float sig_e(float x) {
    return __fdividef(1.0f, 1.0f + __expf(-x));
}

__global__ void k_init() {
    int st = gridDim.x * blockDim.x, e0 = blockIdx.x * blockDim.x + threadIdx.x;
    for (int e = e0; e < SS*HH; e += st) {
        d_corr1[e] = 0.f; d_corr2[e] = 0.f; d_NW0[e] = 0.f; d_S2base[e] = 0.f;
    }
    for (int e = e0; e < NN; e += st) d_lastStep[e] = -1;
}

__global__ void __launch_bounds__(256) k_pre1(
    const float* __restrict__ inputs, const float* __restrict__ nei,
    const float* __restrict__ numNei, const int* __restrict__ seq,
    const float* __restrict__ h0, const float* __restrict__ c0,
    const float* __restrict__ Wg, const float* __restrict__ bg,
    const float* __restrict__ Ws, const float* __restrict__ bs,
    const float* __restrict__ Wn)
{
    const int tid = threadIdx.x, b = blockIdx.x;
    __shared__ float sh[RPB1 * 256];

    for (int e = b*256 + tid; e < NN*HH; e += PRE1_GRID*256) d_cell[e] = c0[e];

    int r0 = b * RPB1;
    int cnt = (r0 < NN) ? min(RPB1, NN - r0) : 0;
    for (int e = tid; e < cnt*256; e += 256) sh[e] = h0[(size_t)r0*256 + e];
    __syncthreads();
    if (cnt > 0) {
        const int h = tid;
        float acc[RPB1];
        #pragma unroll
        for (int r = 0; r < RPB1; ++r) acc[r] = 0.f;
        for (int k = 0; k < 256; ++k) {
            float wv = __ldg(&Wn[k*256 + h]);
            #pragma unroll
            for (int r = 0; r < RPB1; ++r) acc[r] = fmaf(sh[r*256 + k], wv, acc[r]);
        }
        for (int r = 0; r < cnt; ++r) d_HW0[(size_t)(r0+r)*256 + h] = acc[r];
        #pragma unroll
        for (int r = 0; r < RPB1; ++r) acc[r] = 0.f;
        for (int k = 0; k < 256; ++k) {
            float wv = __ldg(&Wg[(256 + k)*256 + h]);
            #pragma unroll
            for (int r = 0; r < RPB1; ++r) acc[r] = fmaf(sh[r*256 + k], wv, acc[r]);
        }
        for (int r = 0; r < cnt; ++r) d_HG0[(size_t)(r0+r)*256 + h] = acc[r];
    }
    __syncthreads();

    if (b < SS) {
        int ii = __ldg(&seq[b]);
        for (int k = tid; k < 256; k += 256) sh[k] = inputs[(size_t)ii*256 + k];
        __syncthreads();
        const int h = tid;
        float fs = bs[h], gi = bg[h];
        for (int k = 0; k < 256; ++k) {
            float iv = sh[k];
            fs = fmaf(iv, __ldg(&Ws[k*256 + h]), fs);
            gi = fmaf(iv, __ldg(&Wg[k*256 + h]), gi);
        }
        d_FS[b*256 + h] = fs;
        d_GI[b*256 + h] = gi;
        // pair-weight table: pairW[b][t'] = nei[seq[t']][seq[b]]
        if (tid < SS) {
            int tseq = __ldg(&seq[tid]);
            d_pairW[b*SS + tid] = __ldg(&nei[(size_t)tseq*NN + ii]);
        }
    }

    if (b == 0 && tid < SS) {
        int me = __ldg(&seq[tid]);
        int lv = -1;
        for (int u = tid - 1; u >= 0; --u)
            if (__ldg(&seq[u]) == me) { lv = u; break; }
        d_lastVisit[tid] = lv;
        atomicMax(&d_lastStep[me], tid);
        d_invN[tid] = 1.0f / __ldg(&numNei[me]);
    }
}

// S2base / NW0: grid (SS/4, NN/512); block does 4 t's x 512 j's for all 256 h
__global__ void __launch_bounds__(256) k_pre2(const float* __restrict__ nei,
                                              const int* __restrict__ seq)
{
    const int tid = threadIdx.x;
    const int tt0 = blockIdx.x * 4, j0 = blockIdx.y * 512;
    __shared__ float shw[4][512];
    int sqs[4];
    #pragma unroll
    for (int q = 0; q < 4; ++q) sqs[q] = __ldg(&seq[tt0 + q]);
    for (int e = tid; e < 4*512; e += 256) {
        int q = e >> 9, j = e & 511;
        shw[q][j] = __ldg(&nei[(size_t)sqs[q]*NN + j0 + j]);
    }
    __syncthreads();
    const int h = tid;
    float fs[4], s1[4], s2[4];
    #pragma unroll
    for (int q = 0; q < 4; ++q) {
        fs[q] = __ldg(&d_FS[(tt0+q)*256 + h]); s1[q] = 0.f; s2[q] = 0.f;
    }
    for (int j = 0; j < 512; ++j) {
        float hw = __ldg(&d_HW0[(size_t)(j0+j)*256 + h]);
        #pragma unroll
        for (int q = 0; q < 4; ++q) {
            float w = shw[q][j];
            s1[q] = fmaf(w, hw, s1[q]);
            s2[q] = fmaf(w, sig_t(fs[q] + hw), s2[q]);
        }
    }
    #pragma unroll
    for (int q = 0; q < 4; ++q) {
        atomicAdd(&d_NW0[(tt0+q)*256 + h], s1[q]);
        atomicAdd(&d_S2base[(tt0+q)*256 + h], s2[q]);
    }
}

// Main serial loop: ONE cluster of 8 CTAs x 1024 threads; cluster.sync per step.
__global__ void __launch_bounds__(MTPB, 1) __cluster_dims__(CTAS, 1, 1)
k_main(const float* __restrict__ Wn, const float* __restrict__ Wg,
       const int* __restrict__ seq)
{
    extern __shared__ float smem[];
    float* shWn  = smem;                 // [32][256] this CTA's Wn columns
    float* shFS  = smem + HPC*256;       // [128][32] FS slice for owned h's
    float* shInv = shFS + SS*HPC;        // [128]
    int*   sseq  = (int*)(shInv + SS);   // [128]
    int*   sslv  = sseq + SS;            // [128]

    const int tid  = threadIdx.x;
    const int wid  = tid >> 5;
    const int lane = tid & 31;
    const int h_base = blockIdx.x * HPC;
    const int h = h_base + wid;          // this warp's owned h-column

    // preamble: load Wn columns (strided, once), FS slice, small tables
    for (int k = lane; k < 256; k += 32)
        shWn[wid*256 + k] = __ldg(&Wn[k*256 + h]);
    for (int e = tid; e < SS*HPC; e += MTPB) {
        int t = e >> 5, hl = e & 31;
        shFS[e] = __ldg(&d_FS[t*256 + h_base + hl]);
    }
    if (tid < SS) {
        sseq[tid]  = __ldg(&seq[tid]);
        sslv[tid]  = d_lastVisit[tid];
        shInv[tid] = d_invN[tid];
    }
    __syncthreads();

    for (int t = 0; t < SS; ++t) {
        const int i  = sseq[t];
        const int lv = sslv[t];
        float hwnew = 0.f, hgdyn = 0.f;

        // --- W1: finalize HWver[t-1] = hidver[t-1] @ Wn (SMEM column)
        if (t > 0) {
            const float4* hv4 = (const float4*)(d_hidver + (t-1)*256);
            const float4* wn4 = (const float4*)(shWn + wid*256);
            #pragma unroll
            for (int q = 0; q < 2; ++q) {
                float4 x = __ldcg(&hv4[lane*2 + q]);
                float4 a = wn4[lane*2 + q];
                hwnew += x.x*a.x + x.y*a.y + x.z*a.z + x.w*a.w;
            }
            #pragma unroll
            for (int o = 16; o; o >>= 1)
                hwnew += __shfl_xor_sync(0xffffffffu, hwnew, o);
            if (lane == 0) __stcg(&d_HWver[(t-1)*256 + h], hwnew);
        }
        // lazy HGi: only when node i was visited before (rare)
        if (lv >= 0) {
            const float* hvp = d_hidver + lv*256;
            #pragma unroll
            for (int q = 0; q < 8; ++q) {
                int k = lane + 32*q;
                hgdyn += __ldcg(&hvp[k]) * __ldg(&Wg[(256 + k)*256 + h]);
            }
            #pragma unroll
            for (int o = 16; o; o >>= 1)
                hgdyn += __shfl_xor_sync(0xffffffffu, hgdyn, o);
        }

        // --- W3: scatter visit u=t-2 into targets t' >= t+1 (owned h slice)
        if (t > 1) {
            const int h3 = h_base + lane;
            float hv = __ldcg(&d_HWver[(t-2)*256 + h3]);
            float hb = __ldcg(&d_HWbef[(t-2)*256 + h3]);
            float dhw = hv - hb;
            const float* pw = d_pairW + (t-2)*SS;
            #pragma unroll 4
            for (int tp = t + 1 + wid; tp < SS; tp += 32) {
                float wp  = __ldg(&pw[tp]);
                float fsp = shFS[tp*HPC + lane];
                int idx = tp*256 + h3;
                __stcg(&d_corr1[idx], __ldcg(&d_corr1[idx]) + wp * dhw);
                __stcg(&d_corr2[idx], __ldcg(&d_corr2[idx]) +
                       wp * (sig_t(fsp + hv) - sig_t(fsp + hb)));
            }
        }

        // --- W2: per-h elementwise update (lane 0 of each warp)
        if (lane == 0) {
            const int tb = t*256 + h;
            float fsv = shFS[t*HPC + wid];
            float S1 = __ldg(&d_NW0[tb])    + __ldcg(&d_corr1[tb]);
            float S2 = __ldg(&d_S2base[tb]) + __ldcg(&d_corr2[tb]);
            if (t > 0) {   // fresh correction: visit t-1
                float w1 = __ldg(&d_pairW[(t-1)*SS + t]);
                float hb = __ldcg(&d_HWbef[(t-1)*256 + h]);
                S1 = fmaf(w1, hwnew - hb, S1);
                S2 = fmaf(w1, sig_t(fsv + hwnew) - sig_t(fsv + hb), S2);
            }
            if (t > 1) {   // fresh correction: visit t-2
                float w2  = __ldg(&d_pairW[(t-2)*SS + t]);
                float hv2 = __ldcg(&d_HWver[(t-2)*256 + h]);
                float hb2 = __ldcg(&d_HWbef[(t-2)*256 + h]);
                S1 = fmaf(w2, hv2 - hb2, S1);
                S2 = fmaf(w2, sig_t(fsv + hv2) - sig_t(fsv + hb2), S2);
            }
            float HWi, HGi;
            if (lv == t-1 && t > 0)  { HWi = hwnew; HGi = hgdyn; }
            else if (lv >= 0)        { HWi = __ldcg(&d_HWver[lv*256 + h]); HGi = hgdyn; }
            else                     { HWi = __ldg(&d_HW0[(size_t)i*256 + h]);
                                       HGi = __ldg(&d_HG0[(size_t)i*256 + h]); }
            float inv_n = shInv[t];
            float pre = __ldg(&d_GI[tb]) + HGi + S1 * inv_n;
            float iS  = sig_e(pre);
            float hC  = fmaf(2.f, sig_e(2.f*pre), -1.f);   // tanh(pre)
            float fS  = sig_e(fsv + HWi);
            float c   = __ldcg(&d_cell[(size_t)i*256 + h]);
            float cC  = fmaf(S2*inv_n, c, fmaf(fS, c, iS*hC));
            __stcg(&d_cell[(size_t)i*256 + h], cC);
            float xx = iS * cC;
            __stcg(&d_hidver[tb], fmaf(2.f, sig_e(2.f*xx), -1.f));  // tanh
            __stcg(&d_HWbef[tb], HWi);
        }

        // --- hardware cluster barrier (release/acquire semantics)
        asm volatile("barrier.cluster.arrive.aligned;" ::: "memory");
        asm volatile("barrier.cluster.wait.aligned;" ::: "memory");
    }
}

__global__ void __launch_bounds__(256) k_epi(const float* __restrict__ h0,
                                             float* __restrict__ out)
{
    for (int e = blockIdx.x*blockDim.x + threadIdx.x; e < NN*HH;
         e += gridDim.x*blockDim.x) {
        int node = e >> 8;
        int ls = __ldg(&d_lastStep[node]);
        float hval = (ls >= 0) ? d_hidver[ls*256 + (e & 255)] : __ldg(&h0[e]);
        out[e] = hval + __ldg(&h0[e]);
    }
}

extern "C" void kernel_launch(void* const* d_in, const int* in_sizes, int n_in,
                              void* d_out, int out_size) {
    const float* inputs  = (const float*)d_in[0];
    const float* nei     = (const float*)d_in[1];
    const float* numNei  = (const float*)d_in[2];
    const int*   seq     = (const int*)  d_in[3];
    const float* h0      = (const float*)d_in[4];
    const float* c0      = (const float*)d_in[5];
    const float* Wg      = (const float*)d_in[6];
    const float* bg      = (const float*)d_in[7];
    const float* Ws      = (const float*)d_in[8];
    const float* bs      = (const float*)d_in[9];
    const float* Wn      = (const float*)d_in[10];
    float* out = (float*)d_out;

    const int smem_main = (HPC*256 + SS*HPC + SS) * 4 + 2*SS*4 + 256;  // ~51KB
    static bool attr_done = false;
    if (!attr_done) {
        cudaFuncSetAttribute(k_main, cudaFuncAttributeMaxDynamicSharedMemorySize,
                             smem_main);
        attr_done = true;
    }

    k_init<<<64, 256>>>();
    k_pre1<<<PRE1_GRID, 256>>>(inputs, nei, numNei, seq, h0, c0, Wg, bg, Ws, bs, Wn);
    k_pre2<<<dim3(SS/4, NN/512), 256>>>(nei, seq);
    k_main<<<CTAS, MTPB, smem_main>>>(Wn, Wg, seq);
    k_epi<<<148, 256>>>(h0, out);
}

// round 8
// speedup vs baseline: 1.5364x; 1.2946x over previous
#include <cuda_runtime.h>

#define NN 4096
#define HH 256
#define SS 128
#define PRE1_GRID 148
#define RPB1 28

#define CTAS 8          // one cluster of 8 CTAs
#define MTPB 1024       // 32 warps per CTA, 1 warp per owned h-column
#define HPC 32          // h-columns per CTA

// ---------------- persistent device scratch ----------------
__device__ __align__(16) float d_HW0[NN*HH];     // h0 @ Wn
__device__ __align__(16) float d_HG0[NN*HH];     // h0 @ Wg_bot
__device__ __align__(16) float d_FS[SS*HH];      // inp_t @ Ws + bs
__device__ __align__(16) float d_GI[SS*HH];      // inp_t @ Wg_top + bg
__device__ __align__(16) float d_NW0[SS*HH];     // (nei_t @ h0) @ Wn
__device__ __align__(16) float d_S2base[SS*HH];  // sum_j w_tj * sig(fs_t + HW0[j])
__device__ __align__(16) float d_hidver[SS*HH];  // curHidden of step t
__device__ __align__(16) float d_pairWT[SS*SS];  // pairWT[t*SS+u] = nei[seq[t]][seq[u]]
__device__ float d_invN[SS];                     // 1 / numNei[seq[t]]
__device__ int   d_lastVisit[SS];                // last u<t with seq[u]==seq[t], else -1
__device__ int   d_lastStep[NN];                 // last step visiting node, else -1

// telescoping sigmoid: 1 MUFU (tanh.approx); identical args cancel bitwise.
__device__ __forceinline__ float sig_t(float x) {
    float t;
    asm("tanh.approx.f32 %0, %1;" : "=f"(t) : "f"(0.5f * x));
    return fmaf(0.5f, t, 0.5f);
}
// accurate sigmoid for own-step gates
__device__ __forceinline__ float sig_e(float x) {
    return __fdividef(1.0f, 1.0f + __expf(-x));
}

__global__ void k_init() {
    int st = gridDim.x * blockDim.x, e0 = blockIdx.x * blockDim.x + threadIdx.x;
    for (int e = e0; e < SS*HH; e += st) { d_NW0[e] = 0.f; d_S2base[e] = 0.f; }
    for (int e = e0; e < NN; e += st) d_lastStep[e] = -1;
}

__global__ void __launch_bounds__(256) k_pre1(
    const float* __restrict__ inputs, const float* __restrict__ nei,
    const float* __restrict__ numNei, const int* __restrict__ seq,
    const float* __restrict__ h0,
    const float* __restrict__ Wg, const float* __restrict__ bg,
    const float* __restrict__ Ws, const float* __restrict__ bs,
    const float* __restrict__ Wn)
{
    const int tid = threadIdx.x, b = blockIdx.x;
    __shared__ float sh[RPB1 * 256];

    int r0 = b * RPB1;
    int cnt = (r0 < NN) ? min(RPB1, NN - r0) : 0;
    for (int e = tid; e < cnt*256; e += 256) sh[e] = h0[(size_t)r0*256 + e];
    __syncthreads();
    if (cnt > 0) {
        const int h = tid;
        float acc[RPB1];
        #pragma unroll
        for (int r = 0; r < RPB1; ++r) acc[r] = 0.f;
        for (int k = 0; k < 256; ++k) {
            float wv = __ldg(&Wn[k*256 + h]);
            #pragma unroll
            for (int r = 0; r < RPB1; ++r) acc[r] = fmaf(sh[r*256 + k], wv, acc[r]);
        }
        for (int r = 0; r < cnt; ++r) d_HW0[(size_t)(r0+r)*256 + h] = acc[r];
        #pragma unroll
        for (int r = 0; r < RPB1; ++r) acc[r] = 0.f;
        for (int k = 0; k < 256; ++k) {
            float wv = __ldg(&Wg[(256 + k)*256 + h]);
            #pragma unroll
            for (int r = 0; r < RPB1; ++r) acc[r] = fmaf(sh[r*256 + k], wv, acc[r]);
        }
        for (int r = 0; r < cnt; ++r) d_HG0[(size_t)(r0+r)*256 + h] = acc[r];
    }
    __syncthreads();

    if (b < SS) {
        int ii = __ldg(&seq[b]);
        for (int k = tid; k < 256; k += 256) sh[k] = inputs[(size_t)ii*256 + k];
        __syncthreads();
        const int h = tid;
        float fs = bs[h], gi = bg[h];
        for (int k = 0; k < 256; ++k) {
            float iv = sh[k];
            fs = fmaf(iv, __ldg(&Ws[k*256 + h]), fs);
            gi = fmaf(iv, __ldg(&Wg[k*256 + h]), gi);
        }
        d_FS[b*256 + h] = fs;
        d_GI[b*256 + h] = gi;
        // transposed pair table: pairWT[t][u] = nei[seq[t]][seq[u]]   (t=tid, u=b)
        if (tid < SS) {
            int tseq = __ldg(&seq[tid]);
            d_pairWT[tid*SS + b] = __ldg(&nei[(size_t)tseq*NN + ii]);
        }
    }

    if (b == 0 && tid < SS) {
        int me = __ldg(&seq[tid]);
        int lv = -1;
        for (int u = tid - 1; u >= 0; --u)
            if (__ldg(&seq[u]) == me) { lv = u; break; }
        d_lastVisit[tid] = lv;
        atomicMax(&d_lastStep[me], tid);
        d_invN[tid] = 1.0f / __ldg(&numNei[me]);
    }
}

// S2base / NW0: grid (SS/4, NN/512)
__global__ void __launch_bounds__(256) k_pre2(const float* __restrict__ nei,
                                              const int* __restrict__ seq)
{
    const int tid = threadIdx.x;
    const int tt0 = blockIdx.x * 4, j0 = blockIdx.y * 512;
    __shared__ float shw[4][512];
    int sqs[4];
    #pragma unroll
    for (int q = 0; q < 4; ++q) sqs[q] = __ldg(&seq[tt0 + q]);
    for (int e = tid; e < 4*512; e += 256) {
        int q = e >> 9, j = e & 511;
        shw[q][j] = __ldg(&nei[(size_t)sqs[q]*NN + j0 + j]);
    }
    __syncthreads();
    const int h = tid;
    float fs[4], s1[4], s2[4];
    #pragma unroll
    for (int q = 0; q < 4; ++q) {
        fs[q] = __ldg(&d_FS[(tt0+q)*256 + h]); s1[q] = 0.f; s2[q] = 0.f;
    }
    for (int j = 0; j < 512; ++j) {
        float hw = __ldg(&d_HW0[(size_t)(j0+j)*256 + h]);
        #pragma unroll
        for (int q = 0; q < 4; ++q) {
            float w = shw[q][j];
            s1[q] = fmaf(w, hw, s1[q]);
            s2[q] = fmaf(w, sig_t(fs[q] + hw), s2[q]);
        }
    }
    #pragma unroll
    for (int q = 0; q < 4; ++q) {
        atomicAdd(&d_NW0[(tt0+q)*256 + h], s1[q]);
        atomicAdd(&d_S2base[(tt0+q)*256 + h], s2[q]);
    }
}

// ---- main serial loop: 1 cluster of 8 CTAs; all hot data in SMEM/registers ----
#define SM_WN    0                       // [32][256]
#define SM_PW    (SM_WN + HPC*256)       // [128][128]
#define SM_FS    (SM_PW + SS*SS)         // [128][32]
#define SM_GIPN  (SM_FS + SS*HPC)
#define SM_S2N   (SM_GIPN + SS*HPC)
#define SM_C0    (SM_S2N + SS*HPC)
#define SM_HW0G  (SM_C0 + SS*HPC)
#define SM_HG0G  (SM_HW0G + SS*HPC)
#define SM_CELL  (SM_HG0G + SS*HPC)
#define SM_INV   (SM_CELL + SS*HPC)      // [128]
#define SM_FLOATS (SM_INV + SS)
#define SM_BYTES  (SM_FLOATS*4 + 2*SS*4)

__global__ void __launch_bounds__(MTPB, 1) __cluster_dims__(CTAS, 1, 1)
k_main(const float* __restrict__ Wn, const float* __restrict__ Wg,
       const int* __restrict__ seq, const float* __restrict__ c0)
{
    extern __shared__ float sm[];
    int* sseq = (int*)(sm + SM_FLOATS);
    int* sslv = sseq + SS;

    const int tid  = threadIdx.x;
    const int wid  = tid >> 5;
    const int lane = tid & 31;
    const int h_base = blockIdx.x * HPC;
    const int h = h_base + wid;

    // -------- preamble: stage all hot data into SMEM --------
    for (int k = lane; k < 256; k += 32)
        sm[SM_WN + wid*256 + k] = __ldg(&Wn[k*256 + h]);
    for (int e = tid; e < SS*SS; e += MTPB)
        sm[SM_PW + e] = d_pairWT[e];
    for (int e = tid; e < SS*HPC; e += MTPB) {
        int t = e >> 5, hl = e & 31;
        int hcol = h_base + hl;
        int node = __ldg(&seq[t]);
        float invn = d_invN[t];
        sm[SM_FS   + e] = d_FS[t*256 + hcol];
        sm[SM_GIPN + e] = d_GI[t*256 + hcol] + d_NW0[t*256 + hcol] * invn;
        sm[SM_S2N  + e] = d_S2base[t*256 + hcol] * invn;
        sm[SM_C0   + e] = __ldg(&c0[(size_t)node*256 + hcol]);
        sm[SM_HW0G + e] = d_HW0[(size_t)node*256 + hcol];
        sm[SM_HG0G + e] = d_HG0[(size_t)node*256 + hcol];
    }
    if (tid < SS) {
        sseq[tid] = __ldg(&seq[tid]);
        sslv[tid] = d_lastVisit[tid];
        sm[SM_INV + tid] = d_invN[tid];
    }
    __syncthreads();

    // per-lane visit-slot caches: slot u = lane + 32*q
    float hv0=0.f,hv1=0.f,hv2=0.f,hv3=0.f;   // HW row AFTER visit u
    float hb0=0.f,hb1=0.f,hb2=0.f,hb3=0.f;   // HW row BEFORE visit u

    for (int t = 0; t < SS; ++t) {
        const int lv = sslv[t];
        const float fsv = sm[SM_FS + t*HPC + wid];
        float hwnew = 0.f;

        // W1: hwnew = hidver[t-1] . Wn[:,h]
        if (t > 0) {
            const float4* hv4 = (const float4*)(d_hidver + (t-1)*256);
            const float4* wn4 = (const float4*)(sm + SM_WN + wid*256);
            float4 x0 = __ldcg(&hv4[lane*2]),   a0 = wn4[lane*2];
            float4 x1 = __ldcg(&hv4[lane*2+1]), a1 = wn4[lane*2+1];
            hwnew = x0.x*a0.x + x0.y*a0.y + x0.z*a0.z + x0.w*a0.w
                  + x1.x*a1.x + x1.y*a1.y + x1.z*a1.z + x1.w*a1.w;
            #pragma unroll
            for (int o = 16; o; o >>= 1)
                hwnew += __shfl_xor_sync(0xffffffffu, hwnew, o);
            // record hv for slot u = t-1
            int slot = t - 1;
            if (lane == (slot & 31)) {
                int q = slot >> 5;
                if (q == 0) hv0 = hwnew; else if (q == 1) hv1 = hwnew;
                else if (q == 2) hv2 = hwnew; else hv3 = hwnew;
            }
        }

        // corrections: sum over visit slots u <= t-1
        float s1c = 0.f, s2c = 0.f;
        {
            const float* pw = sm + SM_PW + t*SS;
            int u0 = lane;
            if (u0 <= t-1) {
                float w = pw[u0], d = hv0 - hb0;
                s1c = fmaf(w, d, s1c);
                s2c = fmaf(w, sig_t(fsv + hv0) - sig_t(fsv + hb0), s2c);
            }
            int u1 = lane + 32;
            if (u1 <= t-1) {
                float w = pw[u1], d = hv1 - hb1;
                s1c = fmaf(w, d, s1c);
                s2c = fmaf(w, sig_t(fsv + hv1) - sig_t(fsv + hb1), s2c);
            }
            int u2 = lane + 64;
            if (u2 <= t-1) {
                float w = pw[u2], d = hv2 - hb2;
                s1c = fmaf(w, d, s1c);
                s2c = fmaf(w, sig_t(fsv + hv2) - sig_t(fsv + hb2), s2c);
            }
            int u3 = lane + 96;
            if (u3 <= t-1) {
                float w = pw[u3], d = hv3 - hb3;
                s1c = fmaf(w, d, s1c);
                s2c = fmaf(w, sig_t(fsv + hv3) - sig_t(fsv + hb3), s2c);
            }
            #pragma unroll
            for (int o = 16; o; o >>= 1) {
                s1c += __shfl_xor_sync(0xffffffffu, s1c, o);
                s2c += __shfl_xor_sync(0xffffffffu, s2c, o);
            }
        }

        // revisit: HWi from slot cache; HGi = hidver[lv] . Wg_bot[:,h] (rare)
        float hv_sel = 0.f, hgdyn = 0.f;
        if (lv >= 0) {
            int q = lv >> 5;
            float s = (q == 0) ? hv0 : (q == 1) ? hv1 : (q == 2) ? hv2 : hv3;
            hv_sel = __shfl_sync(0xffffffffu, s, lv & 31);
            const float* hvp = d_hidver + lv*256;
            #pragma unroll
            for (int qq = 0; qq < 8; ++qq) {
                int k = lane + 32*qq;
                hgdyn += __ldcg(&hvp[k]) * __ldg(&Wg[(256 + k)*256 + h]);
            }
            #pragma unroll
            for (int o = 16; o; o >>= 1)
                hgdyn += __shfl_xor_sync(0xffffffffu, hgdyn, o);
        }

        // W2: lane 0 computes the gates (all operands SMEM/registers)
        float HWi_l0 = 0.f;
        if (lane == 0) {
            const int eb = t*HPC + wid;
            float HWi, HGi, cprev;
            if (lv >= 0) { HWi = hv_sel; HGi = hgdyn; cprev = sm[SM_CELL + lv*HPC + wid]; }
            else         { HWi = sm[SM_HW0G + eb]; HGi = sm[SM_HG0G + eb];
                           cprev = sm[SM_C0 + eb]; }
            float invn = sm[SM_INV + t];
            float pre  = sm[SM_GIPN + eb] + HGi + s1c * invn;
            float S2n  = sm[SM_S2N + eb] + s2c * invn;
            float iS   = sig_e(pre);
            float hC   = fmaf(2.f, sig_e(2.f*pre), -1.f);     // tanh(pre)
            float fS   = sig_e(fsv + HWi);
            float cC   = fmaf(S2n, cprev, fmaf(fS, cprev, iS*hC));
            sm[SM_CELL + eb] = cC;
            float xx = iS * cC;
            __stcg(&d_hidver[t*256 + h], fmaf(2.f, sig_e(2.f*xx), -1.f));  // tanh
            HWi_l0 = HWi;
        }
        // record hb for slot u = t (broadcast HWi from lane 0)
        {
            float HWi_all = __shfl_sync(0xffffffffu, HWi_l0, 0);
            if (lane == (t & 31)) {
                int q = t >> 5;
                if (q == 0) hb0 = HWi_all; else if (q == 1) hb1 = HWi_all;
                else if (q == 2) hb2 = HWi_all; else hb3 = HWi_all;
            }
        }

        asm volatile("barrier.cluster.arrive.aligned;" ::: "memory");
        asm volatile("barrier.cluster.wait.aligned;" ::: "memory");
    }
}

__global__ void __launch_bounds__(256) k_epi(const float* __restrict__ h0,
                                             float* __restrict__ out)
{
    for (int e = blockIdx.x*blockDim.x + threadIdx.x; e < NN*HH;
         e += gridDim.x*blockDim.x) {
        int node = e >> 8;
        int ls = __ldg(&d_lastStep[node]);
        float hval = (ls >= 0) ? d_hidver[ls*256 + (e & 255)] : __ldg(&h0[e]);
        out[e] = hval + __ldg(&h0[e]);
    }
}

extern "C" void kernel_launch(void* const* d_in, const int* in_sizes, int n_in,
                              void* d_out, int out_size) {
    const float* inputs  = (const float*)d_in[0];
    const float* nei     = (const float*)d_in[1];
    const float* numNei  = (const float*)d_in[2];
    const int*   seq     = (const int*)  d_in[3];
    const float* h0      = (const float*)d_in[4];
    const float* c0      = (const float*)d_in[5];
    const float* Wg      = (const float*)d_in[6];
    const float* bg      = (const float*)d_in[7];
    const float* Ws      = (const float*)d_in[8];
    const float* bs      = (const float*)d_in[9];
    const float* Wn      = (const float*)d_in[10];
    float* out = (float*)d_out;

    cudaFuncSetAttribute(k_main, cudaFuncAttributeMaxDynamicSharedMemorySize,
                         SM_BYTES);

    k_init<<<64, 256>>>();
    k_pre1<<<PRE1_GRID, 256>>>(inputs, nei, numNei, seq, h0, Wg, bg, Ws, bs, Wn);
    k_pre2<<<dim3(SS/4, NN/512), 256>>>(nei, seq);
    k_main<<<CTAS, MTPB, SM_BYTES>>>(Wn, Wg, seq, c0);
    k_epi<<<148, 256>>>(h0, out);
}

// round 10
// speedup vs baseline: 1.6033x; 1.0435x over previous
#include <cuda_runtime.h>
#include <cstdint>

#define NN 4096
#define HH 256
#define SS 128
#define PRE1_GRID 148
#define RPB1 28

#define CTAS 8          // one cluster of 8 CTAs
#define MTPB 1024       // 32 warps per CTA, 1 warp per owned h-column
#define HPC 32          // h-columns per CTA

// ---------------- persistent device scratch ----------------
__device__ __align__(16) float d_HW0[NN*HH];     // h0 @ Wn
__device__ __align__(16) float d_HG0[NN*HH];     // h0 @ Wg_bot
__device__ __align__(16) float d_FS[SS*HH];      // inp_t @ Ws + bs
__device__ __align__(16) float d_GI[SS*HH];      // inp_t @ Wg_top + bg
__device__ __align__(16) float d_NW0[SS*HH];     // (nei_t @ h0) @ Wn
__device__ __align__(16) float d_S2base[SS*HH];  // sum_j w_tj * sig(fs_t + HW0[j])
__device__ __align__(16) float d_hidver[SS*HH];  // curHidden of step t (revisits/epi)
__device__ __align__(16) float d_pairWT[SS*SS];  // pairWT[t*SS+u] = nei[seq[t]][seq[u]]
__device__ float d_invN[SS];
__device__ int   d_lastVisit[SS];
__device__ int   d_lastStep[NN];

__device__ __forceinline__ float sig_t(float x) {   // telescoping sigmoid (1 MUFU)
    float t;
    asm("tanh.approx.f32 %0, %1;" : "=f"(t) : "f"(0.5f * x));
    return fmaf(0.5f, t, 0.5f);
}
__device__ __forceinline__ float sig_e(float x) {   // accurate own-step sigmoid
    return __fdividef(1.0f, 1.0f + __expf(-x));
}

__global__ void k_init() {
    int st = gridDim.x * blockDim.x, e0 = blockIdx.x * blockDim.x + threadIdx.x;
    for (int e = e0; e < SS*HH; e += st) { d_NW0[e] = 0.f; d_S2base[e] = 0.f; }
    for (int e = e0; e < NN; e += st) d_lastStep[e] = -1;
}

__global__ void __launch_bounds__(256) k_pre1(
    const float* __restrict__ inputs, const float* __restrict__ nei,
    const float* __restrict__ numNei, const int* __restrict__ seq,
    const float* __restrict__ h0,
    const float* __restrict__ Wg, const float* __restrict__ bg,
    const float* __restrict__ Ws, const float* __restrict__ bs,
    const float* __restrict__ Wn)
{
    const int tid = threadIdx.x, b = blockIdx.x;
    __shared__ float sh[RPB1 * 256];

    int r0 = b * RPB1;
    int cnt = (r0 < NN) ? min(RPB1, NN - r0) : 0;
    for (int e = tid; e < cnt*256; e += 256) sh[e] = h0[(size_t)r0*256 + e];
    __syncthreads();
    if (cnt > 0) {
        const int h = tid;
        float acc[RPB1];
        #pragma unroll
        for (int r = 0; r < RPB1; ++r) acc[r] = 0.f;
        for (int k = 0; k < 256; ++k) {
            float wv = __ldg(&Wn[k*256 + h]);
            #pragma unroll
            for (int r = 0; r < RPB1; ++r) acc[r] = fmaf(sh[r*256 + k], wv, acc[r]);
        }
        for (int r = 0; r < cnt; ++r) d_HW0[(size_t)(r0+r)*256 + h] = acc[r];
        #pragma unroll
        for (int r = 0; r < RPB1; ++r) acc[r] = 0.f;
        for (int k = 0; k < 256; ++k) {
            float wv = __ldg(&Wg[(256 + k)*256 + h]);
            #pragma unroll
            for (int r = 0; r < RPB1; ++r) acc[r] = fmaf(sh[r*256 + k], wv, acc[r]);
        }
        for (int r = 0; r < cnt; ++r) d_HG0[(size_t)(r0+r)*256 + h] = acc[r];
    }
    __syncthreads();

    if (b < SS) {
        int ii = __ldg(&seq[b]);
        for (int k = tid; k < 256; k += 256) sh[k] = inputs[(size_t)ii*256 + k];
        __syncthreads();
        const int h = tid;
        float fs = bs[h], gi = bg[h];
        for (int k = 0; k < 256; ++k) {
            float iv = sh[k];
            fs = fmaf(iv, __ldg(&Ws[k*256 + h]), fs);
            gi = fmaf(iv, __ldg(&Wg[k*256 + h]), gi);
        }
        d_FS[b*256 + h] = fs;
        d_GI[b*256 + h] = gi;
        if (tid < SS) {
            int tseq = __ldg(&seq[tid]);
            d_pairWT[tid*SS + b] = __ldg(&nei[(size_t)tseq*NN + ii]);
        }
    }

    if (b == 0 && tid < SS) {
        int me = __ldg(&seq[tid]);
        int lv = -1;
        for (int u = tid - 1; u >= 0; --u)
            if (__ldg(&seq[u]) == me) { lv = u; break; }
        d_lastVisit[tid] = lv;
        atomicMax(&d_lastStep[me], tid);
        d_invN[tid] = 1.0f / __ldg(&numNei[me]);
    }
}

__global__ void __launch_bounds__(256) k_pre2(const float* __restrict__ nei,
                                              const int* __restrict__ seq)
{
    const int tid = threadIdx.x;
    const int tt0 = blockIdx.x * 4, j0 = blockIdx.y * 512;
    __shared__ float shw[4][512];
    int sqs[4];
    #pragma unroll
    for (int q = 0; q < 4; ++q) sqs[q] = __ldg(&seq[tt0 + q]);
    for (int e = tid; e < 4*512; e += 256) {
        int q = e >> 9, j = e & 511;
        shw[q][j] = __ldg(&nei[(size_t)sqs[q]*NN + j0 + j]);
    }
    __syncthreads();
    const int h = tid;
    float fs[4], s1[4], s2[4];
    #pragma unroll
    for (int q = 0; q < 4; ++q) {
        fs[q] = __ldg(&d_FS[(tt0+q)*256 + h]); s1[q] = 0.f; s2[q] = 0.f;
    }
    for (int j = 0; j < 512; ++j) {
        float hw = __ldg(&d_HW0[(size_t)(j0+j)*256 + h]);
        #pragma unroll
        for (int q = 0; q < 4; ++q) {
            float w = shw[q][j];
            s1[q] = fmaf(w, hw, s1[q]);
            s2[q] = fmaf(w, sig_t(fs[q] + hw), s2[q]);
        }
    }
    #pragma unroll
    for (int q = 0; q < 4; ++q) {
        atomicAdd(&d_NW0[(tt0+q)*256 + h], s1[q]);
        atomicAdd(&d_S2base[(tt0+q)*256 + h], s2[q]);
    }
}

// ---- main serial loop: DSMEM push + monotonic release/acquire flags ----
#define SM_WN    0                       // [32][256]
#define SM_PW    (SM_WN + HPC*256)       // [128][128]
#define SM_FS    (SM_PW + SS*SS)         // [128][32]
#define SM_GIPN  (SM_FS + SS*HPC)
#define SM_S2N   (SM_GIPN + SS*HPC)
#define SM_C0    (SM_S2N + SS*HPC)
#define SM_HW0G  (SM_C0 + SS*HPC)
#define SM_HG0G  (SM_HW0G + SS*HPC)
#define SM_CELL  (SM_HG0G + SS*HPC)
#define SM_INV   (SM_CELL + SS*HPC)      // [128]
#define SM_HIDB  (SM_INV + SS)           // [2][256] hid packet double buffer
#define SM_STAGE (SM_HIDB + 2*HH)        // [2][32] fresh hid staging (parity)
#define SM_FLOATS (SM_STAGE + 64)
#define SM_FLAG_BYTE (((SM_FLOATS + 2*SS)*4 + 15) & ~15)   // 8 u32 flags
#define SM_BYTES (SM_FLAG_BYTE + 32)

__device__ __forceinline__ uint32_t smem_u32(const void* p) {
    uint32_t a;
    asm("{ .reg .u64 t; cvta.to.shared.u64 t, %1; cvt.u32.u64 %0, t; }"
        : "=r"(a) : "l"(p));
    return a;
}
__device__ __forceinline__ uint32_t mapa_rank(uint32_t addr, int rank) {
    uint32_t r;
    asm("mapa.shared::cluster.u32 %0, %1, %2;" : "=r"(r) : "r"(addr), "r"(rank));
    return r;
}
__device__ __forceinline__ unsigned ld_acq_sh(uint32_t addr) {
    unsigned v;
    asm volatile("ld.acquire.cluster.shared::cta.b32 %0, [%1];"
                 : "=r"(v) : "r"(addr) : "memory");
    return v;
}
__device__ __forceinline__ void st_rlx_rem(uint32_t addr, float v) {
    asm volatile("st.relaxed.cluster.shared::cluster.b32 [%0], %1;"
                 :: "r"(addr), "r"(__float_as_uint(v)) : "memory");
}
__device__ __forceinline__ void st_rel_rem(uint32_t addr, unsigned v) {
    asm volatile("st.release.cluster.shared::cluster.b32 [%0], %1;"
                 :: "r"(addr), "r"(v) : "memory");
}

__global__ void __launch_bounds__(MTPB, 1) __cluster_dims__(CTAS, 1, 1)
k_main(const float* __restrict__ Wn, const float* __restrict__ Wg,
       const int* __restrict__ seq, const float* __restrict__ c0)
{
    extern __shared__ __align__(16) float sm[];
    int* sseq = (int*)(sm + SM_FLOATS);
    int* sslv = sseq + SS;
    const uint32_t smbase = smem_u32(sm);
    const uint32_t flagbase = smbase + SM_FLAG_BYTE;

    const int tid  = threadIdx.x;
    const int wid  = tid >> 5;
    const int lane = tid & 31;
    const int rank = blockIdx.x;
    const int h_base = rank * HPC;
    const int h = h_base + wid;

    // -------- preamble: stage all hot data into SMEM --------
    for (int k = lane; k < 256; k += 32)
        sm[SM_WN + wid*256 + k] = __ldg(&Wn[k*256 + h]);
    for (int e = tid; e < SS*SS; e += MTPB)
        sm[SM_PW + e] = d_pairWT[e];
    for (int e = tid; e < SS*HPC; e += MTPB) {
        int t = e >> 5, hl = e & 31;
        int hcol = h_base + hl;
        int node = __ldg(&seq[t]);
        float invn = d_invN[t];
        sm[SM_FS   + e] = d_FS[t*256 + hcol];
        sm[SM_GIPN + e] = d_GI[t*256 + hcol] + d_NW0[t*256 + hcol] * invn;
        sm[SM_S2N  + e] = d_S2base[t*256 + hcol] * invn;
        sm[SM_C0   + e] = __ldg(&c0[(size_t)node*256 + hcol]);
        sm[SM_HW0G + e] = d_HW0[(size_t)node*256 + hcol];
        sm[SM_HG0G + e] = d_HG0[(size_t)node*256 + hcol];
    }
    if (tid < SS) {
        sseq[tid] = __ldg(&seq[tid]);
        sslv[tid] = d_lastVisit[tid];
        sm[SM_INV + tid] = d_invN[tid];
    }
    if (tid < CTAS) ((unsigned*)(sm + (SM_FLAG_BYTE/4)))[tid] = 0u;
    __syncthreads();
    // one-time cluster barrier: flags zeroed in every CTA before anyone pushes
    asm volatile("barrier.cluster.arrive.aligned;" ::: "memory");
    asm volatile("barrier.cluster.wait.aligned;" ::: "memory");

    // per-lane visit-slot caches: slot u = lane + 32*q
    float hv0=0.f,hv1=0.f,hv2=0.f,hv3=0.f;   // HW row AFTER visit u
    float hb0=0.f,hb1=0.f,hb2=0.f,hb3=0.f;   // HW row BEFORE visit u

    for (int t = 0; t < SS; ++t) {
        const int lv = sslv[t];
        const float fsv = sm[SM_FS + t*HPC + wid];
        const int pb = (t - 1) & 1;              // buffer holding hid[t-1]
        float hwnew = 0.f;

        // wait for hid[t-1] packet, then W1: hwnew = hid[t-1] . Wn[:,h]
        if (t > 0) {
            const uint32_t fa = flagbase + 4u * (lane & 7);
            unsigned f = ld_acq_sh(fa);
            while (!__all_sync(0xffffffffu, f >= (unsigned)t))
                f = ld_acq_sh(fa);
            const float4* hv4 = (const float4*)(sm + SM_HIDB + pb*HH);
            const float4* wn4 = (const float4*)(sm + SM_WN + wid*256);
            float4 x0 = hv4[lane*2],   a0 = wn4[lane*2];
            float4 x1 = hv4[lane*2+1], a1 = wn4[lane*2+1];
            hwnew = x0.x*a0.x + x0.y*a0.y + x0.z*a0.z + x0.w*a0.w
                  + x1.x*a1.x + x1.y*a1.y + x1.z*a1.z + x1.w*a1.w;
            #pragma unroll
            for (int o = 16; o; o >>= 1)
                hwnew += __shfl_xor_sync(0xffffffffu, hwnew, o);
            int slot = t - 1;
            if (lane == (slot & 31)) {
                int q = slot >> 5;
                if (q == 0) hv0 = hwnew; else if (q == 1) hv1 = hwnew;
                else if (q == 2) hv2 = hwnew; else hv3 = hwnew;
            }
        }

        // corrections over visit slots u <= t-1
        float s1c = 0.f, s2c = 0.f;
        {
            const float* pw = sm + SM_PW + t*SS;
            if (lane <= t-1) {
                float w = pw[lane];
                s1c = fmaf(w, hv0 - hb0, s1c);
                s2c = fmaf(w, sig_t(fsv + hv0) - sig_t(fsv + hb0), s2c);
            }
            if (lane + 32 <= t-1) {
                float w = pw[lane + 32];
                s1c = fmaf(w, hv1 - hb1, s1c);
                s2c = fmaf(w, sig_t(fsv + hv1) - sig_t(fsv + hb1), s2c);
            }
            if (lane + 64 <= t-1) {
                float w = pw[lane + 64];
                s1c = fmaf(w, hv2 - hb2, s1c);
                s2c = fmaf(w, sig_t(fsv + hv2) - sig_t(fsv + hb2), s2c);
            }
            if (lane + 96 <= t-1) {
                float w = pw[lane + 96];
                s1c = fmaf(w, hv3 - hb3, s1c);
                s2c = fmaf(w, sig_t(fsv + hv3) - sig_t(fsv + hb3), s2c);
            }
            #pragma unroll
            for (int o = 16; o; o >>= 1) {
                s1c += __shfl_xor_sync(0xffffffffu, s1c, o);
                s2c += __shfl_xor_sync(0xffffffffu, s2c, o);
            }
        }

        // revisit: HWi from slot cache; HGi = hid[lv] . Wg_bot[:,h] (rare)
        float hv_sel = 0.f, hgdyn = 0.f;
        if (lv >= 0) {
            int q = lv >> 5;
            float s = (q == 0) ? hv0 : (q == 1) ? hv1 : (q == 2) ? hv2 : hv3;
            hv_sel = __shfl_sync(0xffffffffu, s, lv & 31);
            if (lv == t-1) {
                const float* hvp = sm + SM_HIDB + pb*HH;   // local packet
                #pragma unroll
                for (int qq = 0; qq < 8; ++qq) {
                    int k = lane + 32*qq;
                    hgdyn += hvp[k] * __ldg(&Wg[(256 + k)*256 + h]);
                }
            } else {
                const float* hvp = d_hidver + lv*256;
                #pragma unroll
                for (int qq = 0; qq < 8; ++qq) {
                    int k = lane + 32*qq;
                    hgdyn += __ldcg(&hvp[k]) * __ldg(&Wg[(256 + k)*256 + h]);
                }
            }
            #pragma unroll
            for (int o = 16; o; o >>= 1)
                hgdyn += __shfl_xor_sync(0xffffffffu, hgdyn, o);
        }

        // W2: lane 0 computes gates; stage fresh hid value (parity buffer)
        float HWi_l0 = 0.f;
        if (lane == 0) {
            const int eb = t*HPC + wid;
            float HWi, HGi, cprev;
            if (lv >= 0) { HWi = hv_sel; HGi = hgdyn; cprev = sm[SM_CELL + lv*HPC + wid]; }
            else         { HWi = sm[SM_HW0G + eb]; HGi = sm[SM_HG0G + eb];
                           cprev = sm[SM_C0 + eb]; }
            float invn = sm[SM_INV + t];
            float pre  = sm[SM_GIPN + eb] + HGi + s1c * invn;
            float S2n  = sm[SM_S2N + eb] + s2c * invn;
            float iS   = sig_e(pre);
            float hC   = fmaf(2.f, sig_e(2.f*pre), -1.f);     // tanh(pre)
            float fS   = sig_e(fsv + HWi);
            float cC   = fmaf(S2n, cprev, fmaf(fS, cprev, iS*hC));
            sm[SM_CELL + eb] = cC;
            float xx = iS * cC;
            float hidnew = fmaf(2.f, sig_e(2.f*xx), -1.f);    // tanh
            __stcg(&d_hidver[t*256 + h], hidnew);             // revisits + epilogue
            sm[SM_STAGE + (t & 1)*32 + wid] = hidnew;
            HWi_l0 = HWi;
        }
        // record hb for slot u = t
        {
            float HWi_all = __shfl_sync(0xffffffffu, HWi_l0, 0);
            if (lane == (t & 31)) {
                int q = t >> 5;
                if (q == 0) hb0 = HWi_all; else if (q == 1) hb1 = HWi_all;
                else if (q == 2) hb2 = HWi_all; else hb3 = HWi_all;
            }
        }

        __syncthreads();   // staging complete

        // forwarding: warp d pushes this CTA's 32 values into CTA d's buf[t&1]
        {
            const int p = t & 1;
            if (wid < CTAS) {
                float v = sm[SM_STAGE + p*32 + lane];
                uint32_t loc = smbase + (uint32_t)(SM_HIDB + p*HH + h_base + lane)*4u;
                st_rlx_rem(mapa_rank(loc, wid), v);
                __syncwarp();
                if (lane == 0)
                    st_rel_rem(mapa_rank(flagbase + 4u*rank, wid), (unsigned)(t + 1));
            }
        }
    }
}

__global__ void __launch_bounds__(256) k_epi(const float* __restrict__ h0,
                                             float* __restrict__ out)
{
    for (int e = blockIdx.x*blockDim.x + threadIdx.x; e < NN*HH;
         e += gridDim.x*blockDim.x) {
        int node = e >> 8;
        int ls = __ldg(&d_lastStep[node]);
        float hval = (ls >= 0) ? d_hidver[ls*256 + (e & 255)] : __ldg(&h0[e]);
        out[e] = hval + __ldg(&h0[e]);
    }
}

extern "C" void kernel_launch(void* const* d_in, const int* in_sizes, int n_in,
                              void* d_out, int out_size) {
    const float* inputs  = (const float*)d_in[0];
    const float* nei     = (const float*)d_in[1];
    const float* numNei  = (const float*)d_in[2];
    const int*   seq     = (const int*)  d_in[3];
    const float* h0      = (const float*)d_in[4];
    const float* c0      = (const float*)d_in[5];
    const float* Wg      = (const float*)d_in[6];
    const float* bg      = (const float*)d_in[7];
    const float* Ws      = (const float*)d_in[8];
    const float* bs      = (const float*)d_in[9];
    const float* Wn      = (const float*)d_in[10];
    float* out = (float*)d_out;

    cudaFuncSetAttribute(k_main, cudaFuncAttributeMaxDynamicSharedMemorySize,
                         SM_BYTES);

    k_init<<<64, 256>>>();
    k_pre1<<<PRE1_GRID, 256>>>(inputs, nei, numNei, seq, h0, Wg, bg, Ws, bs, Wn);
    k_pre2<<<dim3(SS/4, NN/512), 256>>>(nei, seq);
    k_main<<<CTAS, MTPB, SM_BYTES>>>(Wn, Wg, seq, c0);
    k_epi<<<148, 256>>>(h0, out);
}

// round 11
// speedup vs baseline: 1.6128x; 1.0059x over previous
#include <cuda_runtime.h>
#include <cstdint>

#define NN 4096
#define HH 256
#define SS 128
#define PRE1_GRID 148
#define RPB1 28

#define CTAS 8          // one cluster of 8 CTAs
#define MTPB 1024       // 32 warps per CTA, 1 warp per owned h-column
#define HPC 32          // h-columns per CTA

// ---------------- persistent device scratch ----------------
__device__ __align__(16) float d_HW0[NN*HH];     // h0 @ Wn
__device__ __align__(16) float d_HG0[NN*HH];     // h0 @ Wg_bot
__device__ __align__(16) float d_FS[SS*HH];      // inp_t @ Ws + bs
__device__ __align__(16) float d_GI[SS*HH];      // inp_t @ Wg_top + bg
__device__ __align__(16) float d_NW0[SS*HH];     // (nei_t @ h0) @ Wn
__device__ __align__(16) float d_S2base[SS*HH];  // sum_j w_tj * sig(fs_t + HW0[j])
__device__ __align__(16) float d_hidver[SS*HH];  // curHidden of step t (revisits/epi)
__device__ __align__(16) float d_pairWT[SS*SS];  // pairWT[t*SS+u] = nei[seq[t]][seq[u]]
__device__ float d_invN[SS];
__device__ int   d_lastVisit[SS];
__device__ int   d_lastStep[NN];

__device__ __forceinline__ float sig_t(float x) {   // telescoping sigmoid (1 MUFU)
    float t;
    asm("tanh.approx.f32 %0, %1;" : "=f"(t) : "f"(0.5f * x));
    return fmaf(0.5f, t, 0.5f);
}
__device__ __forceinline__ float sig_e(float x) {   // accurate own-step sigmoid
    return __fdividef(1.0f, 1.0f + __expf(-x));
}

__global__ void k_init() {
    int st = gridDim.x * blockDim.x, e0 = blockIdx.x * blockDim.x + threadIdx.x;
    for (int e = e0; e < SS*HH; e += st) { d_NW0[e] = 0.f; d_S2base[e] = 0.f; }
    for (int e = e0; e < NN; e += st) d_lastStep[e] = -1;
}

__global__ void __launch_bounds__(256) k_pre1(
    const float* __restrict__ inputs, const float* __restrict__ nei,
    const float* __restrict__ numNei, const int* __restrict__ seq,
    const float* __restrict__ h0,
    const float* __restrict__ Wg, const float* __restrict__ bg,
    const float* __restrict__ Ws, const float* __restrict__ bs,
    const float* __restrict__ Wn)
{
    const int tid = threadIdx.x, b = blockIdx.x;
    __shared__ float sh[RPB1 * 256];

    int r0 = b * RPB1;
    int cnt = (r0 < NN) ? min(RPB1, NN - r0) : 0;
    for (int e = tid; e < cnt*256; e += 256) sh[e] = h0[(size_t)r0*256 + e];
    __syncthreads();
    if (cnt > 0) {
        const int h = tid;
        float acc[RPB1];
        #pragma unroll
        for (int r = 0; r < RPB1; ++r) acc[r] = 0.f;
        for (int k = 0; k < 256; ++k) {
            float wv = __ldg(&Wn[k*256 + h]);
            #pragma unroll
            for (int r = 0; r < RPB1; ++r) acc[r] = fmaf(sh[r*256 + k], wv, acc[r]);
        }
        for (int r = 0; r < cnt; ++r) d_HW0[(size_t)(r0+r)*256 + h] = acc[r];
        #pragma unroll
        for (int r = 0; r < RPB1; ++r) acc[r] = 0.f;
        for (int k = 0; k < 256; ++k) {
            float wv = __ldg(&Wg[(256 + k)*256 + h]);
            #pragma unroll
            for (int r = 0; r < RPB1; ++r) acc[r] = fmaf(sh[r*256 + k], wv, acc[r]);
        }
        for (int r = 0; r < cnt; ++r) d_HG0[(size_t)(r0+r)*256 + h] = acc[r];
    }
    __syncthreads();

    if (b < SS) {
        int ii = __ldg(&seq[b]);
        for (int k = tid; k < 256; k += 256) sh[k] = inputs[(size_t)ii*256 + k];
        __syncthreads();
        const int h = tid;
        float fs = bs[h], gi = bg[h];
        for (int k = 0; k < 256; ++k) {
            float iv = sh[k];
            fs = fmaf(iv, __ldg(&Ws[k*256 + h]), fs);
            gi = fmaf(iv, __ldg(&Wg[k*256 + h]), gi);
        }
        d_FS[b*256 + h] = fs;
        d_GI[b*256 + h] = gi;
        if (tid < SS) {
            int tseq = __ldg(&seq[tid]);
            d_pairWT[tid*SS + b] = __ldg(&nei[(size_t)tseq*NN + ii]);
        }
    }

    if (b == 0 && tid < SS) {
        int me = __ldg(&seq[tid]);
        int lv = -1;
        for (int u = tid - 1; u >= 0; --u)
            if (__ldg(&seq[u]) == me) { lv = u; break; }
        d_lastVisit[tid] = lv;
        atomicMax(&d_lastStep[me], tid);
        d_invN[tid] = 1.0f / __ldg(&numNei[me]);
    }
}

// S2base / NW0: 8 t's x 512 j's per block; grid (16, 8) = 128 blocks = 1 wave
#define T_PER 8
__global__ void __launch_bounds__(256) k_pre2(const float* __restrict__ nei,
                                              const int* __restrict__ seq)
{
    const int tid = threadIdx.x;
    const int tt0 = blockIdx.x * T_PER, j0 = blockIdx.y * 512;
    __shared__ float shw[T_PER][512];
    int sqs[T_PER];
    #pragma unroll
    for (int q = 0; q < T_PER; ++q) sqs[q] = __ldg(&seq[tt0 + q]);
    for (int e = tid; e < T_PER*512; e += 256) {
        int q = e >> 9, j = e & 511;
        shw[q][j] = __ldg(&nei[(size_t)sqs[q]*NN + j0 + j]);
    }
    __syncthreads();
    const int h = tid;
    float fs[T_PER], s1[T_PER], s2[T_PER];
    #pragma unroll
    for (int q = 0; q < T_PER; ++q) {
        fs[q] = __ldg(&d_FS[(tt0+q)*256 + h]); s1[q] = 0.f; s2[q] = 0.f;
    }
    #pragma unroll 2
    for (int j = 0; j < 512; ++j) {
        float hw = __ldg(&d_HW0[(size_t)(j0+j)*256 + h]);
        #pragma unroll
        for (int q = 0; q < T_PER; ++q) {
            float w = shw[q][j];
            s1[q] = fmaf(w, hw, s1[q]);
            s2[q] = fmaf(w, sig_t(fs[q] + hw), s2[q]);
        }
    }
    #pragma unroll
    for (int q = 0; q < T_PER; ++q) {
        atomicAdd(&d_NW0[(tt0+q)*256 + h], s1[q]);
        atomicAdd(&d_S2base[(tt0+q)*256 + h], s2[q]);
    }
}

// ---- main serial loop: DSMEM direct push + monotonic flags; corr overlapped ----
#define SM_WN    0                       // [32][256]
#define SM_PW    (SM_WN + HPC*256)       // [128][128]
#define SM_FS    (SM_PW + SS*SS)         // [128][32]
#define SM_GIPN  (SM_FS + SS*HPC)
#define SM_S2N   (SM_GIPN + SS*HPC)
#define SM_C0    (SM_S2N + SS*HPC)
#define SM_HW0G  (SM_C0 + SS*HPC)
#define SM_HG0G  (SM_HW0G + SS*HPC)
#define SM_CELL  (SM_HG0G + SS*HPC)
#define SM_INV   (SM_CELL + SS*HPC)      // [128]
#define SM_HIDB  (SM_INV + SS)           // [2][256] hid packet double buffer
#define SM_FLOATS (SM_HIDB + 2*HH)
#define SM_FLAG_BYTE (((SM_FLOATS + 2*SS)*4 + 15) & ~15)   // 8 u32 flags
#define SM_BYTES (SM_FLAG_BYTE + 32)

__device__ __forceinline__ uint32_t smem_u32(const void* p) {
    uint32_t a;
    asm("{ .reg .u64 t; cvta.to.shared.u64 t, %1; cvt.u32.u64 %0, t; }"
        : "=r"(a) : "l"(p));
    return a;
}
__device__ __forceinline__ uint32_t mapa_rank(uint32_t addr, int rank) {
    uint32_t r;
    asm("mapa.shared::cluster.u32 %0, %1, %2;" : "=r"(r) : "r"(addr), "r"(rank));
    return r;
}
__device__ __forceinline__ unsigned ld_acq_sh(uint32_t addr) {
    unsigned v;
    asm volatile("ld.acquire.cluster.shared::cta.b32 %0, [%1];"
                 : "=r"(v) : "r"(addr) : "memory");
    return v;
}
__device__ __forceinline__ void st_rlx_rem(uint32_t addr, float v) {
    asm volatile("st.relaxed.cluster.shared::cluster.b32 [%0], %1;"
                 :: "r"(addr), "r"(__float_as_uint(v)) : "memory");
}
__device__ __forceinline__ void st_rel_rem(uint32_t addr, unsigned v) {
    asm volatile("st.release.cluster.shared::cluster.b32 [%0], %1;"
                 :: "r"(addr), "r"(v) : "memory");
}

__global__ void __launch_bounds__(MTPB, 1) __cluster_dims__(CTAS, 1, 1)
k_main(const float* __restrict__ Wn, const float* __restrict__ Wg,
       const int* __restrict__ seq, const float* __restrict__ c0)
{
    extern __shared__ __align__(16) float sm[];
    int* sseq = (int*)(sm + SM_FLOATS);
    int* sslv = sseq + SS;
    const uint32_t smbase = smem_u32(sm);
    const uint32_t flagbase = smbase + SM_FLAG_BYTE;

    const int tid  = threadIdx.x;
    const int wid  = tid >> 5;
    const int lane = tid & 31;
    const int rank = blockIdx.x;
    const int h_base = rank * HPC;
    const int h = h_base + wid;

    // -------- preamble: stage all hot data into SMEM --------
    for (int k = lane; k < 256; k += 32)
        sm[SM_WN + wid*256 + k] = __ldg(&Wn[k*256 + h]);
    for (int e = tid; e < SS*SS; e += MTPB)
        sm[SM_PW + e] = d_pairWT[e];
    for (int e = tid; e < SS*HPC; e += MTPB) {
        int t = e >> 5, hl = e & 31;
        int hcol = h_base + hl;
        int node = __ldg(&seq[t]);
        float invn = d_invN[t];
        sm[SM_FS   + e] = d_FS[t*256 + hcol];
        sm[SM_GIPN + e] = d_GI[t*256 + hcol] + d_NW0[t*256 + hcol] * invn;
        sm[SM_S2N  + e] = d_S2base[t*256 + hcol] * invn;
        sm[SM_C0   + e] = __ldg(&c0[(size_t)node*256 + hcol]);
        sm[SM_HW0G + e] = d_HW0[(size_t)node*256 + hcol];
        sm[SM_HG0G + e] = d_HG0[(size_t)node*256 + hcol];
    }
    if (tid < SS) {
        sseq[tid] = __ldg(&seq[tid]);
        sslv[tid] = d_lastVisit[tid];
        sm[SM_INV + tid] = d_invN[tid];
    }
    if (tid < CTAS) ((unsigned*)(sm + (SM_FLAG_BYTE/4)))[tid] = 0u;
    __syncthreads();
    // one-time cluster barrier: flags zeroed everywhere before anyone pushes
    asm volatile("barrier.cluster.arrive.aligned;" ::: "memory");
    asm volatile("barrier.cluster.wait.aligned;" ::: "memory");

    // per-lane visit-slot caches: slot u = lane + 32*q
    float hv0=0.f,hv1=0.f,hv2=0.f,hv3=0.f;   // HW row AFTER visit u
    float hb0=0.f,hb1=0.f,hb2=0.f,hb3=0.f;   // HW row BEFORE visit u

    for (int t = 0; t < SS; ++t) {
        const int lv = sslv[t];
        const float fsv = sm[SM_FS + t*HPC + wid];
        const int pb = (t - 1) & 1;
        const float* pw = sm + SM_PW + t*SS;

        // ===== pre-wait (overlaps previous step's communication) =====
        // corr over visit slots u <= t-2
        float s1c = 0.f, s2c = 0.f;
        const int lim = t - 2;
        if (lane <= lim) {
            float w = pw[lane];
            s1c = fmaf(w, hv0 - hb0, s1c);
            s2c = fmaf(w, sig_t(fsv + hv0) - sig_t(fsv + hb0), s2c);
        }
        if (lane + 32 <= lim) {
            float w = pw[lane + 32];
            s1c = fmaf(w, hv1 - hb1, s1c);
            s2c = fmaf(w, sig_t(fsv + hv1) - sig_t(fsv + hb1), s2c);
        }
        if (lane + 64 <= lim) {
            float w = pw[lane + 64];
            s1c = fmaf(w, hv2 - hb2, s1c);
            s2c = fmaf(w, sig_t(fsv + hv2) - sig_t(fsv + hb2), s2c);
        }
        if (lane + 96 <= lim) {
            float w = pw[lane + 96];
            s1c = fmaf(w, hv3 - hb3, s1c);
            s2c = fmaf(w, sig_t(fsv + hv3) - sig_t(fsv + hb3), s2c);
        }

        // revisit prep (lv <= t-2): HWi from slot cache, HGi via global dot
        float hv_sel = 0.f, hgdyn = 0.f;
        const bool lv_old = (lv >= 0) && (lv < t - 1);
        if (lv_old) {
            int q = lv >> 5;
            float s = (q == 0) ? hv0 : (q == 1) ? hv1 : (q == 2) ? hv2 : hv3;
            hv_sel = __shfl_sync(0xffffffffu, s, lv & 31);
            const float* hvp = d_hidver + lv*256;
            #pragma unroll
            for (int qq = 0; qq < 8; ++qq) {
                int k = lane + 32*qq;
                hgdyn += __ldcg(&hvp[k]) * __ldg(&Wg[(256 + k)*256 + h]);
            }
            #pragma unroll
            for (int o = 16; o; o >>= 1)
                hgdyn += __shfl_xor_sync(0xffffffffu, hgdyn, o);
        }
        // early HWi / fS for the lv != t-1 cases
        float HWi_e = lv_old ? hv_sel : sm[SM_HW0G + t*HPC + wid];
        float fS_e = 0.f;
        if (lane == 0 && lv != t - 1) fS_e = sig_e(fsv + HWi_e);

        // ===== wait for hid[t-1] packet =====
        if (t > 0) {
            unsigned ok;
            do {
                unsigned f = (lane < CTAS) ? ld_acq_sh(flagbase + 4u*lane) : 0u;
                ok = __all_sync(0xffffffffu,
                                (lane < CTAS) ? (f >= (unsigned)t) : 1u);
            } while (!ok);
        }

        // ===== post-wait: dot + slot-(t-1) correction =====
        float hwnew = 0.f;
        if (t > 0) {
            const float4* hv4 = (const float4*)(sm + SM_HIDB + pb*HH);
            const float4* wn4 = (const float4*)(sm + SM_WN + wid*256);
            float4 x0 = hv4[lane*2],   a0 = wn4[lane*2];
            float4 x1 = hv4[lane*2+1], a1 = wn4[lane*2+1];
            hwnew = x0.x*a0.x + x0.y*a0.y + x0.z*a0.z + x0.w*a0.w
                  + x1.x*a1.x + x1.y*a1.y + x1.z*a1.z + x1.w*a1.w;
            #pragma unroll
            for (int o = 16; o; o >>= 1)
                hwnew += __shfl_xor_sync(0xffffffffu, hwnew, o);
            const int slot = t - 1;
            if (lane == (slot & 31)) {
                int q = slot >> 5;
                float hbp;
                if (q == 0)      { hbp = hb0; hv0 = hwnew; }
                else if (q == 1) { hbp = hb1; hv1 = hwnew; }
                else if (q == 2) { hbp = hb2; hv2 = hwnew; }
                else             { hbp = hb3; hv3 = hwnew; }
                float w = pw[slot];
                s1c = fmaf(w, hwnew - hbp, s1c);
                s2c = fmaf(w, sig_t(fsv + hwnew) - sig_t(fsv + hbp), s2c);
            }
        }
        #pragma unroll
        for (int o = 16; o; o >>= 1) {
            s1c += __shfl_xor_sync(0xffffffffu, s1c, o);
            s2c += __shfl_xor_sync(0xffffffffu, s2c, o);
        }

        // rare: revisit of the immediately preceding step
        if (lv == t - 1 && t > 0) {
            const float* hvp = sm + SM_HIDB + pb*HH;
            float g = 0.f;
            #pragma unroll
            for (int qq = 0; qq < 8; ++qq) {
                int k = lane + 32*qq;
                g += hvp[k] * __ldg(&Wg[(256 + k)*256 + h]);
            }
            #pragma unroll
            for (int o = 16; o; o >>= 1)
                g += __shfl_xor_sync(0xffffffffu, g, o);
            hgdyn = g;
            hv_sel = hwnew;
        }

        // ===== gates (lane 0) =====
        float hid_l0 = 0.f, HWi_l0 = 0.f;
        if (lane == 0) {
            const int eb = t*HPC + wid;
            float HWi, HGi, cprev, fS;
            if (lv >= 0) { HWi = hv_sel; HGi = hgdyn;
                           cprev = sm[SM_CELL + lv*HPC + wid]; }
            else         { HWi = HWi_e; HGi = sm[SM_HG0G + eb];
                           cprev = sm[SM_C0 + eb]; }
            fS = (lv == t - 1) ? sig_e(fsv + HWi) : fS_e;
            float invn = sm[SM_INV + t];
            float pre  = sm[SM_GIPN + eb] + HGi + s1c * invn;
            float S2n  = sm[SM_S2N + eb] + s2c * invn;
            float iS   = sig_e(pre);
            float hC   = fmaf(2.f, sig_e(2.f*pre), -1.f);     // tanh(pre)
            float cC   = fmaf(S2n, cprev, fmaf(fS, cprev, iS*hC));
            sm[SM_CELL + eb] = cC;
            float xx = iS * cC;
            hid_l0 = fmaf(2.f, sig_e(2.f*xx), -1.f);          // tanh
            __stcg(&d_hidver[t*256 + h], hid_l0);             // revisits + epilogue
            HWi_l0 = HWi;
        }
        // record hb for slot u = t
        float hidnew = __shfl_sync(0xffffffffu, hid_l0, 0);
        float HWi_all = __shfl_sync(0xffffffffu, HWi_l0, 0);
        if (lane == (t & 31)) {
            int q = t >> 5;
            if (q == 0) hb0 = HWi_all; else if (q == 1) hb1 = HWi_all;
            else if (q == 2) hb2 = HWi_all; else hb3 = HWi_all;
        }

        // direct push: lanes 0..7 send this warp's value to all 8 CTAs
        if (lane < CTAS) {
            uint32_t loc = smbase + (uint32_t)(SM_HIDB + (t & 1)*HH + h) * 4u;
            st_rlx_rem(mapa_rank(loc, lane), hidnew);
        }

        // intra-CTA arrival; warp0 releases flags to all CTAs
        if (wid == 0) {
            asm volatile("bar.sync 1, %0;" :: "r"(MTPB) : "memory");
            if (lane < CTAS)
                st_rel_rem(mapa_rank(flagbase + 4u*rank, lane), (unsigned)(t + 1));
        } else {
            asm volatile("bar.arrive 1, %0;" :: "r"(MTPB) : "memory");
        }
    }

    // final cluster barrier: no CTA exits with peers' remote ops in flight
    asm volatile("barrier.cluster.arrive.aligned;" ::: "memory");
    asm volatile("barrier.cluster.wait.aligned;" ::: "memory");
}

__global__ void __launch_bounds__(256) k_epi(const float* __restrict__ h0,
                                             float* __restrict__ out)
{
    for (int e = blockIdx.x*blockDim.x + threadIdx.x; e < NN*HH;
         e += gridDim.x*blockDim.x) {
        int node = e >> 8;
        int ls = __ldg(&d_lastStep[node]);
        float hval = (ls >= 0) ? d_hidver[ls*256 + (e & 255)] : __ldg(&h0[e]);
        out[e] = hval + __ldg(&h0[e]);
    }
}

extern "C" void kernel_launch(void* const* d_in, const int* in_sizes, int n_in,
                              void* d_out, int out_size) {
    const float* inputs  = (const float*)d_in[0];
    const float* nei     = (const float*)d_in[1];
    const float* numNei  = (const float*)d_in[2];
    const int*   seq     = (const int*)  d_in[3];
    const float* h0      = (const float*)d_in[4];
    const float* c0      = (const float*)d_in[5];
    const float* Wg      = (const float*)d_in[6];
    const float* bg      = (const float*)d_in[7];
    const float* Ws      = (const float*)d_in[8];
    const float* bs      = (const float*)d_in[9];
    const float* Wn      = (const float*)d_in[10];
    float* out = (float*)d_out;

    cudaFuncSetAttribute(k_main, cudaFuncAttributeMaxDynamicSharedMemorySize,
                         SM_BYTES);

    k_init<<<64, 256>>>();
    k_pre1<<<PRE1_GRID, 256>>>(inputs, nei, numNei, seq, h0, Wg, bg, Ws, bs, Wn);
    k_pre2<<<dim3(SS/T_PER, NN/512), 256>>>(nei, seq);
    k_main<<<CTAS, MTPB, SM_BYTES>>>(Wn, Wg, seq, c0);
    k_epi<<<148, 256>>>(h0, out);
}

// round 12
// speedup vs baseline: 1.8086x; 1.1214x over previous
#include <cuda_runtime.h>
#include <cstdint>

#define NN 4096
#define HH 256
#define SS 128
#define RPB1 32

// ---------------- persistent device scratch ----------------
__device__ __align__(16) float d_HW0[NN*HH];     // h0 @ Wn
__device__ __align__(16) float d_HG0[NN*HH];     // h0 @ Wg_bot
__device__ __align__(16) float d_FS[SS*HH];      // inp_t @ Ws + bs
__device__ __align__(16) float d_GI[SS*HH];      // inp_t @ Wg_top + bg
__device__ __align__(16) float d_NW0p[8][SS*HH]; // partial (nei_t @ h0) @ Wn
__device__ __align__(16) float d_S2p[8][SS*HH];  // partial S2base
__device__ __align__(16) float d_hidver[SS*HH];  // curHidden of step t
__device__ __align__(16) float d_pairWT[SS*SS];  // pairWT[t*SS+u] = nei[seq[t]][seq[u]]
__device__ float d_invN[SS];
__device__ int   d_lastVisit[SS];
__device__ int   d_lastStep[NN];

__device__ __forceinline__ float sig_t(float x) {   // sigmoid via tanh.approx (1 MUFU)
    float t;
    asm("tanh.approx.f32 %0, %1;" : "=f"(t) : "f"(0.5f * x));
    return fmaf(0.5f, t, 0.5f);
}
__device__ __forceinline__ float tanh_a(float x) {  // tanh.approx (1 MUFU)
    float t;
    asm("tanh.approx.f32 %0, %1;" : "=f"(t) : "f"(x));
    return t;
}

__global__ void k_init() {
    int e = blockIdx.x * blockDim.x + threadIdx.x;
    if (e < NN) d_lastStep[e] = -1;
}

__global__ void __launch_bounds__(256) k_pre1(
    const float* __restrict__ inputs, const float* __restrict__ nei,
    const float* __restrict__ numNei, const int* __restrict__ seq,
    const float* __restrict__ h0,
    const float* __restrict__ Wg, const float* __restrict__ bg,
    const float* __restrict__ Ws, const float* __restrict__ bs,
    const float* __restrict__ Wn)
{
    const int tid = threadIdx.x, b = blockIdx.x;
    __shared__ float sh[RPB1 * 256];

    const int r0 = b * RPB1;
    for (int e = tid; e < RPB1*256; e += 256) sh[e] = h0[(size_t)r0*256 + e];
    __syncthreads();
    {
        const int h = tid;
        float acc[RPB1];
        #pragma unroll
        for (int r = 0; r < RPB1; ++r) acc[r] = 0.f;
        for (int k = 0; k < 256; ++k) {
            float wv = __ldg(&Wn[k*256 + h]);
            #pragma unroll
            for (int r = 0; r < RPB1; ++r) acc[r] = fmaf(sh[r*256 + k], wv, acc[r]);
        }
        #pragma unroll
        for (int r = 0; r < RPB1; ++r) d_HW0[(size_t)(r0+r)*256 + h] = acc[r];
        #pragma unroll
        for (int r = 0; r < RPB1; ++r) acc[r] = 0.f;
        for (int k = 0; k < 256; ++k) {
            float wv = __ldg(&Wg[(256 + k)*256 + h]);
            #pragma unroll
            for (int r = 0; r < RPB1; ++r) acc[r] = fmaf(sh[r*256 + k], wv, acc[r]);
        }
        #pragma unroll
        for (int r = 0; r < RPB1; ++r) d_HG0[(size_t)(r0+r)*256 + h] = acc[r];
    }
    __syncthreads();

    {   // b in [0, SS): FS/GI for step b + pairWT column
        int ii = __ldg(&seq[b]);
        for (int k = tid; k < 256; k += 256) sh[k] = inputs[(size_t)ii*256 + k];
        __syncthreads();
        const int h = tid;
        float fs = bs[h], gi = bg[h];
        for (int k = 0; k < 256; ++k) {
            float iv = sh[k];
            fs = fmaf(iv, __ldg(&Ws[k*256 + h]), fs);
            gi = fmaf(iv, __ldg(&Wg[k*256 + h]), gi);
        }
        d_FS[b*256 + h] = fs;
        d_GI[b*256 + h] = gi;
        if (tid < SS) {
            int tseq = __ldg(&seq[tid]);
            d_pairWT[tid*SS + b] = __ldg(&nei[(size_t)tseq*NN + ii]);
        }
    }

    if (b == 0 && tid < SS) {
        int me = __ldg(&seq[tid]);
        int lv = -1;
        for (int u = tid - 1; u >= 0; --u)
            if (__ldg(&seq[u]) == me) { lv = u; break; }
        d_lastVisit[tid] = lv;
        atomicMax(&d_lastStep[me], tid);
        d_invN[tid] = 1.0f / __ldg(&numNei[me]);
    }
}

// S2base / NW0 partials: 8 t's x 512 j's per block; grid (16, 8) = 128 blocks
#define T_PER 8
__global__ void __launch_bounds__(256) k_pre2(const float* __restrict__ nei,
                                              const int* __restrict__ seq)
{
    const int tid = threadIdx.x;
    const int tt0 = blockIdx.x * T_PER, j0 = blockIdx.y * 512, by = blockIdx.y;
    __shared__ float shw[T_PER][512];
    int sqs[T_PER];
    #pragma unroll
    for (int q = 0; q < T_PER; ++q) sqs[q] = __ldg(&seq[tt0 + q]);
    for (int e = tid; e < T_PER*512; e += 256) {
        int q = e >> 9, j = e & 511;
        shw[q][j] = __ldg(&nei[(size_t)sqs[q]*NN + j0 + j]);
    }
    __syncthreads();
    const int h = tid;
    float fs[T_PER], s1[T_PER], s2[T_PER];
    #pragma unroll
    for (int q = 0; q < T_PER; ++q) {
        fs[q] = __ldg(&d_FS[(tt0+q)*256 + h]); s1[q] = 0.f; s2[q] = 0.f;
    }
    #pragma unroll 2
    for (int j = 0; j < 512; ++j) {
        float hw = __ldg(&d_HW0[(size_t)(j0+j)*256 + h]);
        #pragma unroll
        for (int q = 0; q < T_PER; ++q) {
            float w = shw[q][j];
            s1[q] = fmaf(w, hw, s1[q]);
            s2[q] = fmaf(w, sig_t(fs[q] + hw), s2[q]);
        }
    }
    #pragma unroll
    for (int q = 0; q < T_PER; ++q) {
        d_NW0p[by][(tt0+q)*256 + h] = s1[q];
        d_S2p [by][(tt0+q)*256 + h] = s2[q];
    }
}

// ---------------- main serial loop (templated on cluster size) ----------------
template<int NCTA> struct Cfg {
    static constexpr int W    = 256 / NCTA;      // warps per CTA (1 per owned h)
    static constexpr int NT   = W * 32;
    static constexpr int O_WN   = 0;             // [W][256]
    static constexpr int O_PW   = O_WN + W*256;  // [SS][SS]
    static constexpr int O_FS   = O_PW + SS*SS;  // [SS][W]
    static constexpr int O_GIPN = O_FS + SS*W;
    static constexpr int O_S2N  = O_GIPN + SS*W;
    static constexpr int O_C0   = O_S2N + SS*W;
    static constexpr int O_HW0G = O_C0 + SS*W;
    static constexpr int O_HG0G = O_HW0G + SS*W;
    static constexpr int O_CELL = O_HG0G + SS*W;
    static constexpr int O_INV  = O_CELL + SS*W; // [SS]
    static constexpr int O_HIDB = O_INV + SS;    // [2][256]
    static constexpr int O_END  = O_HIDB + 2*HH;
    static constexpr int FLAG_BYTE = ((O_END*4 + SS*4) + 15) & ~15;
    static constexpr int SMB = FLAG_BYTE + 64;
};

__device__ __forceinline__ uint32_t smem_u32(const void* p) {
    uint32_t a;
    asm("{ .reg .u64 t; cvta.to.shared.u64 t, %1; cvt.u32.u64 %0, t; }"
        : "=r"(a) : "l"(p));
    return a;
}
__device__ __forceinline__ uint32_t mapa_rank(uint32_t addr, int rank) {
    uint32_t r;
    asm("mapa.shared::cluster.u32 %0, %1, %2;" : "=r"(r) : "r"(addr), "r"(rank));
    return r;
}
__device__ __forceinline__ unsigned ld_acq_sh(uint32_t addr) {
    unsigned v;
    asm volatile("ld.acquire.cluster.shared::cta.b32 %0, [%1];"
                 : "=r"(v) : "r"(addr) : "memory");
    return v;
}
__device__ __forceinline__ void st_rlx_rem(uint32_t addr, float v) {
    asm volatile("st.relaxed.cluster.shared::cluster.b32 [%0], %1;"
                 :: "r"(addr), "r"(__float_as_uint(v)) : "memory");
}
__device__ __forceinline__ void st_rel_rem(uint32_t addr, unsigned v) {
    asm volatile("st.release.cluster.shared::cluster.b32 [%0], %1;"
                 :: "r"(addr), "r"(v) : "memory");
}

template<int NCTA>
__device__ __forceinline__ void k_main_body(
    const float* __restrict__ Wn, const float* __restrict__ Wg,
    const int* __restrict__ seq, const float* __restrict__ c0)
{
    using C = Cfg<NCTA>;
    constexpr int W = C::W;
    extern __shared__ __align__(16) float sm[];
    int* sslv = (int*)(sm + C::O_END);
    const uint32_t smbase = smem_u32(sm);
    const uint32_t flagbase = smbase + C::FLAG_BYTE;

    const int tid  = threadIdx.x;
    const int wid  = tid >> 5;
    const int lane = tid & 31;
    const int rank = blockIdx.x;
    const int h_base = rank * W;
    const int h = h_base + wid;

    // -------- preamble --------
    for (int k = lane; k < 256; k += 32)
        sm[C::O_WN + wid*256 + k] = __ldg(&Wn[k*256 + h]);
    for (int e = tid; e < SS*SS; e += C::NT)
        sm[C::O_PW + e] = d_pairWT[e];
    for (int e = tid; e < SS*W; e += C::NT) {
        int t = e / W, hl = e % W;
        int hcol = h_base + hl;
        int node = __ldg(&seq[t]);
        float invn = d_invN[t];
        float nv = 0.f, s2v = 0.f;
        #pragma unroll
        for (int p = 0; p < 8; ++p) {
            nv  += d_NW0p[p][t*256 + hcol];
            s2v += d_S2p [p][t*256 + hcol];
        }
        sm[C::O_FS   + e] = d_FS[t*256 + hcol];
        sm[C::O_GIPN + e] = d_GI[t*256 + hcol] + nv * invn;
        sm[C::O_S2N  + e] = s2v * invn;
        sm[C::O_C0   + e] = __ldg(&c0[(size_t)node*256 + hcol]);
        sm[C::O_HW0G + e] = d_HW0[(size_t)node*256 + hcol];
        sm[C::O_HG0G + e] = d_HG0[(size_t)node*256 + hcol];
    }
    if (tid < SS) {
        sslv[tid] = d_lastVisit[tid];
        sm[C::O_INV + tid] = d_invN[tid];
    }
    if (tid < NCTA) ((unsigned*)(sm + (C::FLAG_BYTE/4)))[tid] = 0u;
    __syncthreads();
    asm volatile("barrier.cluster.arrive.aligned;" ::: "memory");
    asm volatile("barrier.cluster.wait.aligned;" ::: "memory");

    // per-lane visit-slot caches: slot u = lane + 32*q
    float hv0=0.f,hv1=0.f,hv2=0.f,hv3=0.f;
    float hb0=0.f,hb1=0.f,hb2=0.f,hb3=0.f;

    for (int t = 0; t < SS; ++t) {
        const int lv = sslv[t];
        const float fsv = sm[C::O_FS + t*W + wid];
        const int pb = (t - 1) & 1;
        const float* pw = sm + C::O_PW + t*SS;

        // ===== pre-wait (overlaps previous step's communication) =====
        float s1p = 0.f, s2p = 0.f;
        const int lim = t - 2;
        if (lane <= lim) {
            float w = pw[lane];
            s1p = fmaf(w, hv0 - hb0, s1p);
            s2p = fmaf(w, sig_t(fsv + hv0) - sig_t(fsv + hb0), s2p);
        }
        if (lane + 32 <= lim) {
            float w = pw[lane + 32];
            s1p = fmaf(w, hv1 - hb1, s1p);
            s2p = fmaf(w, sig_t(fsv + hv1) - sig_t(fsv + hb1), s2p);
        }
        if (lane + 64 <= lim) {
            float w = pw[lane + 64];
            s1p = fmaf(w, hv2 - hb2, s1p);
            s2p = fmaf(w, sig_t(fsv + hv2) - sig_t(fsv + hb2), s2p);
        }
        if (lane + 96 <= lim) {
            float w = pw[lane + 96];
            s1p = fmaf(w, hv3 - hb3, s1p);
            s2p = fmaf(w, sig_t(fsv + hv3) - sig_t(fsv + hb3), s2p);
        }
        #pragma unroll
        for (int o = 16; o; o >>= 1) {          // full reduce pre-wait
            s1p += __shfl_xor_sync(0xffffffffu, s1p, o);
            s2p += __shfl_xor_sync(0xffffffffu, s2p, o);
        }

        // revisit prep (lv <= t-2)
        float hv_sel = 0.f, hgdyn = 0.f;
        const bool lv_old = (lv >= 0) && (lv < t - 1);
        if (lv_old) {
            int q = lv >> 5;
            float s = (q == 0) ? hv0 : (q == 1) ? hv1 : (q == 2) ? hv2 : hv3;
            hv_sel = __shfl_sync(0xffffffffu, s, lv & 31);
            const float* hvp = d_hidver + lv*256;
            #pragma unroll
            for (int qq = 0; qq < 8; ++qq) {
                int k = lane + 32*qq;
                hgdyn += __ldcg(&hvp[k]) * __ldg(&Wg[(256 + k)*256 + h]);
            }
            #pragma unroll
            for (int o = 16; o; o >>= 1)
                hgdyn += __shfl_xor_sync(0xffffffffu, hgdyn, o);
        }
        float HWi_e = lv_old ? hv_sel : sm[C::O_HW0G + t*W + wid];
        float fS_e = 0.f;
        if (lane == 0 && lv != t - 1) fS_e = sig_t(fsv + HWi_e);

        // ===== wait for hid[t-1] packet =====
        if (t > 0) {
            unsigned ok;
            do {
                unsigned f = (lane < NCTA) ? ld_acq_sh(flagbase + 4u*lane) : 0u;
                ok = __all_sync(0xffffffffu,
                                (lane < NCTA) ? (f >= (unsigned)t) : 1u);
            } while (!ok);
        }

        // ===== post-wait: dot + slot-(t-1) correction =====
        float hwnew = 0.f, c1 = 0.f, c2 = 0.f;
        if (t > 0) {
            const float4* hv4 = (const float4*)(sm + C::O_HIDB + pb*HH);
            const float4* wn4 = (const float4*)(sm + C::O_WN + wid*256);
            float4 x0 = hv4[lane*2],   a0 = wn4[lane*2];
            float4 x1 = hv4[lane*2+1], a1 = wn4[lane*2+1];
            hwnew = x0.x*a0.x + x0.y*a0.y + x0.z*a0.z + x0.w*a0.w
                  + x1.x*a1.x + x1.y*a1.y + x1.z*a1.z + x1.w*a1.w;
            #pragma unroll
            for (int o = 16; o; o >>= 1)
                hwnew += __shfl_xor_sync(0xffffffffu, hwnew, o);
            const int slot = t - 1, owner = slot & 31, q = slot >> 5;
            if (lane == owner) {
                float hbp;
                if (q == 0)      { hbp = hb0; hv0 = hwnew; }
                else if (q == 1) { hbp = hb1; hv1 = hwnew; }
                else if (q == 2) { hbp = hb2; hv2 = hwnew; }
                else             { hbp = hb3; hv3 = hwnew; }
                float w = pw[slot];
                c1 = w * (hwnew - hbp);
                c2 = w * (sig_t(fsv + hwnew) - sig_t(fsv + hbp));
            }
            c1 = __shfl_sync(0xffffffffu, c1, owner);
            c2 = __shfl_sync(0xffffffffu, c2, owner);
        }

        // rare: revisit of immediately preceding step
        if (lv == t - 1 && t > 0) {
            const float* hvp = sm + C::O_HIDB + pb*HH;
            float g = 0.f;
            #pragma unroll
            for (int qq = 0; qq < 8; ++qq) {
                int k = lane + 32*qq;
                g += hvp[k] * __ldg(&Wg[(256 + k)*256 + h]);
            }
            #pragma unroll
            for (int o = 16; o; o >>= 1)
                g += __shfl_xor_sync(0xffffffffu, g, o);
            hgdyn = g;
            hv_sel = hwnew;
        }

        // ===== gates (lane 0), all MUFU via tanh.approx =====
        float hid_l0 = 0.f, HWi_l0 = 0.f;
        if (lane == 0) {
            const int eb = t*W + wid;
            float HWi, HGi, cprev, fS;
            if (lv >= 0) { HWi = hv_sel; HGi = hgdyn;
                           cprev = sm[C::O_CELL + lv*W + wid]; }
            else         { HWi = HWi_e; HGi = sm[C::O_HG0G + eb];
                           cprev = sm[C::O_C0 + eb]; }
            fS = (lv == t - 1) ? sig_t(fsv + HWi) : fS_e;
            float invn = sm[C::O_INV + t];
            float pre  = sm[C::O_GIPN + eb] + HGi + (s1p + c1) * invn;
            float S2n  = sm[C::O_S2N + eb] + (s2p + c2) * invn;
            float iS   = sig_t(pre);
            float hC   = tanh_a(pre);
            float cC   = fmaf(S2n, cprev, fmaf(fS, cprev, iS*hC));
            sm[C::O_CELL + eb] = cC;
            hid_l0 = tanh_a(iS * cC);
            __stcg(&d_hidver[t*256 + h], hid_l0);
            HWi_l0 = HWi;
        }
        float hidnew  = __shfl_sync(0xffffffffu, hid_l0, 0);
        float HWi_all = __shfl_sync(0xffffffffu, HWi_l0, 0);
        if (lane == (t & 31)) {
            int q = t >> 5;
            if (q == 0) hb0 = HWi_all; else if (q == 1) hb1 = HWi_all;
            else if (q == 2) hb2 = HWi_all; else hb3 = HWi_all;
        }

        // direct push to all NCTA CTAs
        if (lane < NCTA) {
            uint32_t loc = smbase + (uint32_t)(C::O_HIDB + (t & 1)*HH + h) * 4u;
            st_rlx_rem(mapa_rank(loc, lane), hidnew);
        }
        if (wid == 0) {
            asm volatile("bar.sync 1, %0;" :: "r"(C::NT) : "memory");
            if (lane < NCTA)
                st_rel_rem(mapa_rank(flagbase + 4u*rank, lane), (unsigned)(t + 1));
        } else {
            asm volatile("bar.arrive 1, %0;" :: "r"(C::NT) : "memory");
        }
    }

    asm volatile("barrier.cluster.arrive.aligned;" ::: "memory");
    asm volatile("barrier.cluster.wait.aligned;" ::: "memory");
}

__global__ void __launch_bounds__(1024, 1) __cluster_dims__(8, 1, 1)
k_main8(const float* __restrict__ Wn, const float* __restrict__ Wg,
        const int* __restrict__ seq, const float* __restrict__ c0)
{ k_main_body<8>(Wn, Wg, seq, c0); }

__global__ void __launch_bounds__(512, 1)
k_main16(const float* __restrict__ Wn, const float* __restrict__ Wg,
         const int* __restrict__ seq, const float* __restrict__ c0)
{ k_main_body<16>(Wn, Wg, seq, c0); }

__global__ void __launch_bounds__(256) k_epi(const float* __restrict__ h0,
                                             float* __restrict__ out)
{
    for (int e = blockIdx.x*blockDim.x + threadIdx.x; e < NN*HH;
         e += gridDim.x*blockDim.x) {
        int node = e >> 8;
        int ls = __ldg(&d_lastStep[node]);
        float hval = (ls >= 0) ? d_hidver[ls*256 + (e & 255)] : __ldg(&h0[e]);
        out[e] = hval + __ldg(&h0[e]);
    }
}

extern "C" void kernel_launch(void* const* d_in, const int* in_sizes, int n_in,
                              void* d_out, int out_size) {
    const float* inputs  = (const float*)d_in[0];
    const float* nei     = (const float*)d_in[1];
    const float* numNei  = (const float*)d_in[2];
    const int*   seq     = (const int*)  d_in[3];
    const float* h0      = (const float*)d_in[4];
    const float* c0      = (const float*)d_in[5];
    const float* Wg      = (const float*)d_in[6];
    const float* bg      = (const float*)d_in[7];
    const float* Ws      = (const float*)d_in[8];
    const float* bs      = (const float*)d_in[9];
    const float* Wn      = (const float*)d_in[10];
    float* out = (float*)d_out;

    static int ncta_sel = 0;   // deterministic config choice, resolved once
    if (ncta_sel == 0) {
        cudaFuncSetAttribute(k_main8, cudaFuncAttributeMaxDynamicSharedMemorySize,
                             Cfg<8>::SMB);
        int ok16 = 0;
        if (cudaFuncSetAttribute(k_main16,
                cudaFuncAttributeNonPortableClusterSizeAllowed, 1) == cudaSuccess &&
            cudaFuncSetAttribute(k_main16,
                cudaFuncAttributeMaxDynamicSharedMemorySize, Cfg<16>::SMB) == cudaSuccess) {
            cudaLaunchConfig_t cfg = {};
            cfg.gridDim = dim3(16, 1, 1);
            cfg.blockDim = dim3(512, 1, 1);
            cfg.dynamicSmemBytes = Cfg<16>::SMB;
            cudaLaunchAttribute a[1];
            a[0].id = cudaLaunchAttributeClusterDimension;
            a[0].val.clusterDim = {16, 1, 1};
            cfg.attrs = a; cfg.numAttrs = 1;
            int num = 0;
            if (cudaOccupancyMaxActiveClusters(&num, k_main16, &cfg) == cudaSuccess
                && num >= 1)
                ok16 = 1;
        }
        cudaGetLastError();    // clear any probe error
        ncta_sel = ok16 ? 16 : 8;
    }

    k_init<<<16, 256>>>();
    k_pre1<<<SS, 256>>>(inputs, nei, numNei, seq, h0, Wg, bg, Ws, bs, Wn);
    k_pre2<<<dim3(SS/T_PER, NN/512), 256>>>(nei, seq);
    if (ncta_sel == 16) {
        cudaLaunchConfig_t cfg = {};
        cfg.gridDim = dim3(16, 1, 1);
        cfg.blockDim = dim3(512, 1, 1);
        cfg.dynamicSmemBytes = Cfg<16>::SMB;
        cudaLaunchAttribute a[1];
        a[0].id = cudaLaunchAttributeClusterDimension;
        a[0].val.clusterDim = {16, 1, 1};
        cfg.attrs = a; cfg.numAttrs = 1;
        cudaLaunchKernelEx(&cfg, k_main16, Wn, Wg, seq, c0);
    } else {
        k_main8<<<8, 1024, Cfg<8>::SMB>>>(Wn, Wg, seq, c0);
    }
    k_epi<<<148, 256>>>(h0, out);
}

// round 14
// speedup vs baseline: 2.0934x; 1.1575x over previous
#include <cuda_runtime.h>
#include <cstdint>

#define NN 4096
#define HH 256
#define SS 128
#define RPB1 32

// ---------------- persistent device scratch ----------------
__device__ __align__(16) float d_HW0[NN*HH];     // h0 @ Wn
__device__ __align__(16) float d_HG0[NN*HH];     // h0 @ Wg_bot
__device__ __align__(16) float d_FS[SS*HH];      // inp_t @ Ws + bs
__device__ __align__(16) float d_GI[SS*HH];      // inp_t @ Wg_top + bg
__device__ __align__(16) float d_NW0p[8][SS*HH]; // partial (nei_t @ h0) @ Wn
__device__ __align__(16) float d_S2p[8][SS*HH];  // partial S2base
__device__ __align__(16) float d_hidver[SS*HH];  // curHidden of step t
__device__ __align__(16) float d_pairWT[SS*SS];  // pairWT[t*SS+u] = nei[seq[t]][seq[u]]
__device__ float d_invN[SS];
__device__ int   d_lastVisit[SS];
__device__ int   d_lastStep[NN];

__device__ __forceinline__ float sig_t(float x) {   // sigmoid via tanh.approx (1 MUFU)
    float t;
    asm("tanh.approx.f32 %0, %1;" : "=f"(t) : "f"(0.5f * x));
    return fmaf(0.5f, t, 0.5f);
}
__device__ __forceinline__ float tanh_a(float x) {  // tanh.approx (1 MUFU)
    float t;
    asm("tanh.approx.f32 %0, %1;" : "=f"(t) : "f"(x));
    return t;
}
__device__ __forceinline__ float redux_add(float v) {  // warp sum (shfl butterfly)
    #pragma unroll
    for (int o = 16; o; o >>= 1)
        v += __shfl_xor_sync(0xffffffffu, v, o);
    return v;
}

__global__ void k_init() {
    int e = blockIdx.x * blockDim.x + threadIdx.x;
    if (e < NN) d_lastStep[e] = -1;
}

__global__ void __launch_bounds__(256) k_pre1(
    const float* __restrict__ inputs, const float* __restrict__ nei,
    const float* __restrict__ numNei, const int* __restrict__ seq,
    const float* __restrict__ h0,
    const float* __restrict__ Wg, const float* __restrict__ bg,
    const float* __restrict__ Ws, const float* __restrict__ bs,
    const float* __restrict__ Wn)
{
    const int tid = threadIdx.x, b = blockIdx.x;
    __shared__ float sh[RPB1 * 256];

    const int r0 = b * RPB1;
    for (int e = tid; e < RPB1*256; e += 256) sh[e] = h0[(size_t)r0*256 + e];
    __syncthreads();
    {
        const int hq = (tid & 63) * 4;     // 4 h-columns per thread
        const int rg = (tid >> 6) * 8;     // 8 rows per thread
        float acc[8][4];
        #pragma unroll
        for (int r = 0; r < 8; ++r)
            #pragma unroll
            for (int c = 0; c < 4; ++c) acc[r][c] = 0.f;
        for (int k = 0; k < 256; ++k) {
            float4 wv = *(const float4*)&Wn[k*256 + hq];
            #pragma unroll
            for (int r = 0; r < 8; ++r) {
                float a = sh[(rg + r)*256 + k];
                acc[r][0] = fmaf(a, wv.x, acc[r][0]);
                acc[r][1] = fmaf(a, wv.y, acc[r][1]);
                acc[r][2] = fmaf(a, wv.z, acc[r][2]);
                acc[r][3] = fmaf(a, wv.w, acc[r][3]);
            }
        }
        #pragma unroll
        for (int r = 0; r < 8; ++r)
            *(float4*)&d_HW0[(size_t)(r0 + rg + r)*256 + hq] =
                make_float4(acc[r][0], acc[r][1], acc[r][2], acc[r][3]);
        #pragma unroll
        for (int r = 0; r < 8; ++r)
            #pragma unroll
            for (int c = 0; c < 4; ++c) acc[r][c] = 0.f;
        for (int k = 0; k < 256; ++k) {
            float4 wv = *(const float4*)&Wg[(256 + k)*256 + hq];
            #pragma unroll
            for (int r = 0; r < 8; ++r) {
                float a = sh[(rg + r)*256 + k];
                acc[r][0] = fmaf(a, wv.x, acc[r][0]);
                acc[r][1] = fmaf(a, wv.y, acc[r][1]);
                acc[r][2] = fmaf(a, wv.z, acc[r][2]);
                acc[r][3] = fmaf(a, wv.w, acc[r][3]);
            }
        }
        #pragma unroll
        for (int r = 0; r < 8; ++r)
            *(float4*)&d_HG0[(size_t)(r0 + rg + r)*256 + hq] =
                make_float4(acc[r][0], acc[r][1], acc[r][2], acc[r][3]);
    }
    __syncthreads();

    {   // b in [0, SS): FS/GI for step b + pairWT column
        int ii = __ldg(&seq[b]);
        for (int k = tid; k < 256; k += 256) sh[k] = inputs[(size_t)ii*256 + k];
        __syncthreads();
        const int h = tid;
        float fs = bs[h], gi = bg[h];
        for (int k = 0; k < 256; ++k) {
            float iv = sh[k];
            fs = fmaf(iv, __ldg(&Ws[k*256 + h]), fs);
            gi = fmaf(iv, __ldg(&Wg[k*256 + h]), gi);
        }
        d_FS[b*256 + h] = fs;
        d_GI[b*256 + h] = gi;
        if (tid < SS) {
            int tseq = __ldg(&seq[tid]);
            d_pairWT[tid*SS + b] = __ldg(&nei[(size_t)tseq*NN + ii]);
        }
    }

    if (b == 0 && tid < SS) {
        int me = __ldg(&seq[tid]);
        int lv = -1;
        for (int u = tid - 1; u >= 0; --u)
            if (__ldg(&seq[u]) == me) { lv = u; break; }
        d_lastVisit[tid] = lv;
        atomicMax(&d_lastStep[me], tid);
        d_invN[tid] = 1.0f / __ldg(&numNei[me]);
    }
}

// S2base / NW0 partials: 8 t's x 512 j's per block; grid (16, 8) = 128 blocks
#define T_PER 8
__global__ void __launch_bounds__(256) k_pre2(const float* __restrict__ nei,
                                              const int* __restrict__ seq)
{
    const int tid = threadIdx.x;
    const int tt0 = blockIdx.x * T_PER, j0 = blockIdx.y * 512, by = blockIdx.y;
    __shared__ float shw[T_PER][512];
    int sqs[T_PER];
    #pragma unroll
    for (int q = 0; q < T_PER; ++q) sqs[q] = __ldg(&seq[tt0 + q]);
    for (int e = tid; e < T_PER*512; e += 256) {
        int q = e >> 9, j = e & 511;
        shw[q][j] = __ldg(&nei[(size_t)sqs[q]*NN + j0 + j]);
    }
    __syncthreads();
    const int h = tid;
    float fs[T_PER], s1[T_PER], s2[T_PER];
    #pragma unroll
    for (int q = 0; q < T_PER; ++q) {
        fs[q] = __ldg(&d_FS[(tt0+q)*256 + h]); s1[q] = 0.f; s2[q] = 0.f;
    }
    #pragma unroll 2
    for (int j = 0; j < 512; ++j) {
        float hw = __ldg(&d_HW0[(size_t)(j0+j)*256 + h]);
        #pragma unroll
        for (int q = 0; q < T_PER; ++q) {
            float w = shw[q][j];
            s1[q] = fmaf(w, hw, s1[q]);
            s2[q] = fmaf(w, sig_t(fs[q] + hw), s2[q]);
        }
    }
    #pragma unroll
    for (int q = 0; q < T_PER; ++q) {
        d_NW0p[by][(tt0+q)*256 + h] = s1[q];
        d_S2p [by][(tt0+q)*256 + h] = s2[q];
    }
}

// ---------------- main serial loop (templated on cluster size) ----------------
template<int NCTA> struct Cfg {
    static constexpr int W    = 256 / NCTA;      // warps per CTA (1 per owned h)
    static constexpr int NT   = W * 32;
    static constexpr int O_WN   = 0;             // [W][256]
    static constexpr int O_PW   = O_WN + W*256;  // [SS][SS]
    static constexpr int O_FS   = O_PW + SS*SS;  // [SS][W]
    static constexpr int O_GIPN = O_FS + SS*W;
    static constexpr int O_S2N  = O_GIPN + SS*W;
    static constexpr int O_C0   = O_S2N + SS*W;
    static constexpr int O_HW0G = O_C0 + SS*W;
    static constexpr int O_HG0G = O_HW0G + SS*W;
    static constexpr int O_CELL = O_HG0G + SS*W;
    static constexpr int O_INV  = O_CELL + SS*W; // [SS]
    static constexpr int O_HIDB = O_INV + SS;    // [2][256]
    static constexpr int O_END  = O_HIDB + 2*HH;
    static constexpr int FLAG_BYTE = ((O_END*4 + SS*4) + 15) & ~15;
    static constexpr int SMB = FLAG_BYTE + 128;  // flags[NCTA] + relcnt
};

__device__ __forceinline__ uint32_t smem_u32(const void* p) {
    uint32_t a;
    asm("{ .reg .u64 t; cvta.to.shared.u64 t, %1; cvt.u32.u64 %0, t; }"
        : "=r"(a) : "l"(p));
    return a;
}
__device__ __forceinline__ uint32_t mapa_rank(uint32_t addr, int rank) {
    uint32_t r;
    asm("mapa.shared::cluster.u32 %0, %1, %2;" : "=r"(r) : "r"(addr), "r"(rank));
    return r;
}
__device__ __forceinline__ unsigned ld_acq_sh(uint32_t addr) {
    unsigned v;
    asm volatile("ld.acquire.cluster.shared::cta.b32 %0, [%1];"
                 : "=r"(v) : "r"(addr) : "memory");
    return v;
}
__device__ __forceinline__ void st_rel_rem_f(uint32_t addr, float v) {
    asm volatile("st.release.cluster.shared::cluster.b32 [%0], %1;"
                 :: "r"(addr), "r"(__float_as_uint(v)) : "memory");
}
__device__ __forceinline__ void st_rel_rem(uint32_t addr, unsigned v) {
    asm volatile("st.release.cluster.shared::cluster.b32 [%0], %1;"
                 :: "r"(addr), "r"(v) : "memory");
}

template<int NCTA>
__device__ __forceinline__ void k_main_body(
    const float* __restrict__ Wn, const float* __restrict__ Wg,
    const int* __restrict__ seq, const float* __restrict__ c0)
{
    using C = Cfg<NCTA>;
    constexpr int W = C::W;
    extern __shared__ __align__(16) float sm[];
    int* sslv = (int*)(sm + C::O_END);
    const uint32_t smbase = smem_u32(sm);
    const uint32_t flagbase = smbase + C::FLAG_BYTE;
    unsigned* relcnt = (unsigned*)(sm + C::FLAG_BYTE/4 + NCTA);

    const int tid  = threadIdx.x;
    const int wid  = tid >> 5;
    const int lane = tid & 31;
    const int rank = blockIdx.x;
    const int h_base = rank * W;
    const int h = h_base + wid;

    // -------- preamble --------
    for (int k = lane; k < 256; k += 32)
        sm[C::O_WN + wid*256 + k] = __ldg(&Wn[k*256 + h]);
    for (int e = tid; e < SS*SS; e += C::NT)
        sm[C::O_PW + e] = d_pairWT[e];
    for (int e = tid; e < SS*W; e += C::NT) {
        int t = e / W, hl = e % W;
        int hcol = h_base + hl;
        int node = __ldg(&seq[t]);
        float invn = d_invN[t];
        float nv = 0.f, s2v = 0.f;
        #pragma unroll
        for (int p = 0; p < 8; ++p) {
            nv  += d_NW0p[p][t*256 + hcol];
            s2v += d_S2p [p][t*256 + hcol];
        }
        sm[C::O_FS   + e] = d_FS[t*256 + hcol];
        sm[C::O_GIPN + e] = d_GI[t*256 + hcol] + nv * invn;
        sm[C::O_S2N  + e] = s2v * invn;
        sm[C::O_C0   + e] = __ldg(&c0[(size_t)node*256 + hcol]);
        sm[C::O_HW0G + e] = d_HW0[(size_t)node*256 + hcol];
        sm[C::O_HG0G + e] = d_HG0[(size_t)node*256 + hcol];
    }
    if (tid < SS) {
        sslv[tid] = d_lastVisit[tid];
        sm[C::O_INV + tid] = d_invN[tid];
    }
    if (tid < NCTA) ((unsigned*)(sm + (C::FLAG_BYTE/4)))[tid] = 0u;
    if (tid == 0) *relcnt = 0u;
    __syncthreads();
    asm volatile("barrier.cluster.arrive.aligned;" ::: "memory");
    asm volatile("barrier.cluster.wait.aligned;" ::: "memory");

    // per-lane visit-slot caches: slot u = lane + 32*q
    float hv0=0.f,hv1=0.f,hv2=0.f,hv3=0.f;
    float hb0=0.f,hb1=0.f,hb2=0.f,hb3=0.f;

    for (int t = 0; t < SS; ++t) {
        const int lv = sslv[t];
        const float fsv = sm[C::O_FS + t*W + wid];
        const int pb = (t - 1) & 1;
        const float* pw = sm + C::O_PW + t*SS;

        // ===== pre-wait (overlaps previous step's communication) =====
        float s1p = 0.f, s2p = 0.f;
        const int lim = t - 2;
        if (lane <= lim) {
            float w = pw[lane];
            s1p = fmaf(w, hv0 - hb0, s1p);
            s2p = fmaf(w, sig_t(fsv + hv0) - sig_t(fsv + hb0), s2p);
        }
        if (lane + 32 <= lim) {
            float w = pw[lane + 32];
            s1p = fmaf(w, hv1 - hb1, s1p);
            s2p = fmaf(w, sig_t(fsv + hv1) - sig_t(fsv + hb1), s2p);
        }
        if (lane + 64 <= lim) {
            float w = pw[lane + 64];
            s1p = fmaf(w, hv2 - hb2, s1p);
            s2p = fmaf(w, sig_t(fsv + hv2) - sig_t(fsv + hb2), s2p);
        }
        if (lane + 96 <= lim) {
            float w = pw[lane + 96];
            s1p = fmaf(w, hv3 - hb3, s1p);
            s2p = fmaf(w, sig_t(fsv + hv3) - sig_t(fsv + hb3), s2p);
        }
        #pragma unroll
        for (int o = 16; o; o >>= 1) {
            s1p += __shfl_xor_sync(0xffffffffu, s1p, o);
            s2p += __shfl_xor_sync(0xffffffffu, s2p, o);
        }

        // revisit prep (lv <= t-2)
        float hv_sel = 0.f, hgdyn = 0.f;
        const bool lv_old = (lv >= 0) && (lv < t - 1);
        if (lv_old) {
            int q = lv >> 5;
            float s = (q == 0) ? hv0 : (q == 1) ? hv1 : (q == 2) ? hv2 : hv3;
            hv_sel = __shfl_sync(0xffffffffu, s, lv & 31);
            float g = 0.f;
            const float* hvp = d_hidver + lv*256;
            #pragma unroll
            for (int qq = 0; qq < 8; ++qq) {
                int k = lane + 32*qq;
                g += __ldcg(&hvp[k]) * __ldg(&Wg[(256 + k)*256 + h]);
            }
            hgdyn = redux_add(g);
        }
        float HWi_e = lv_old ? hv_sel : sm[C::O_HW0G + t*W + wid];
        float fS_e = 0.f;
        if (lane == 0 && lv != t - 1) fS_e = sig_t(fsv + HWi_e);

        // ===== merged wait: warp 0 polls, everyone meets at bar 2 =====
        if (t > 0 && wid == 0) {
            unsigned ok;
            do {
                unsigned f = (lane < NCTA) ? ld_acq_sh(flagbase + 4u*lane) : 0u;
                ok = __all_sync(0xffffffffu,
                                (lane < NCTA) ? (f >= (unsigned)t) : 1u);
            } while (!ok);
        }
        asm volatile("bar.sync 2, %0;" :: "r"(C::NT) : "memory");

        // ===== post-wait: dot + slot-(t-1) correction =====
        float hwnew = 0.f, c1 = 0.f, c2 = 0.f;
        if (t > 0) {
            const float4* hv4 = (const float4*)(sm + C::O_HIDB + pb*HH);
            const float4* wn4 = (const float4*)(sm + C::O_WN + wid*256);
            float4 x0 = hv4[lane*2],   a0 = wn4[lane*2];
            float4 x1 = hv4[lane*2+1], a1 = wn4[lane*2+1];
            float d = x0.x*a0.x + x0.y*a0.y + x0.z*a0.z + x0.w*a0.w
                    + x1.x*a1.x + x1.y*a1.y + x1.z*a1.z + x1.w*a1.w;
            hwnew = redux_add(d);
            const int slot = t - 1, owner = slot & 31, q = slot >> 5;
            if (lane == owner) {
                float hbp;
                if (q == 0)      { hbp = hb0; hv0 = hwnew; }
                else if (q == 1) { hbp = hb1; hv1 = hwnew; }
                else if (q == 2) { hbp = hb2; hv2 = hwnew; }
                else             { hbp = hb3; hv3 = hwnew; }
                float w = pw[slot];
                c1 = w * (hwnew - hbp);
                c2 = w * (sig_t(fsv + hwnew) - sig_t(fsv + hbp));
            }
            c1 = __shfl_sync(0xffffffffu, c1, owner);
            c2 = __shfl_sync(0xffffffffu, c2, owner);
        }

        // rare: revisit of immediately preceding step
        if (lv == t - 1 && t > 0) {
            const float* hvp = sm + C::O_HIDB + pb*HH;
            float g = 0.f;
            #pragma unroll
            for (int qq = 0; qq < 8; ++qq) {
                int k = lane + 32*qq;
                g += hvp[k] * __ldg(&Wg[(256 + k)*256 + h]);
            }
            hgdyn = redux_add(g);
            hv_sel = hwnew;
        }

        // ===== gates (lane 0), MUFU via tanh.approx =====
        float hid_l0 = 0.f, HWi_l0 = 0.f;
        if (lane == 0) {
            const int eb = t*W + wid;
            float HWi, HGi, cprev, fS;
            if (lv >= 0) { HWi = hv_sel; HGi = hgdyn;
                           cprev = sm[C::O_CELL + lv*W + wid]; }
            else         { HWi = HWi_e; HGi = sm[C::O_HG0G + eb];
                           cprev = sm[C::O_C0 + eb]; }
            fS = (lv == t - 1) ? sig_t(fsv + HWi) : fS_e;
            float invn = sm[C::O_INV + t];
            float pre  = sm[C::O_GIPN + eb] + HGi + (s1p + c1) * invn;
            float S2n  = sm[C::O_S2N + eb] + (s2p + c2) * invn;
            float iS   = sig_t(pre);
            float hC   = tanh_a(pre);
            float cC   = fmaf(S2n, cprev, fmaf(fS, cprev, iS*hC));
            sm[C::O_CELL + eb] = cC;
            hid_l0 = tanh_a(iS * cC);
            __stcg(&d_hidver[t*256 + h], hid_l0);
            HWi_l0 = HWi;
        }
        float hidnew  = __shfl_sync(0xffffffffu, hid_l0, 0);
        float HWi_all = __shfl_sync(0xffffffffu, HWi_l0, 0);
        if (lane == (t & 31)) {
            int q = t >> 5;
            if (q == 0) hb0 = HWi_all; else if (q == 1) hb1 = HWi_all;
            else if (q == 2) hb2 = HWi_all; else hb3 = HWi_all;
        }

        // ===== push: release-store to all NCTA CTAs; last warp releases flags =====
        if (lane < NCTA) {
            uint32_t loc = smbase + (uint32_t)(C::O_HIDB + (t & 1)*HH + h) * 4u;
            st_rel_rem_f(mapa_rank(loc, lane), hidnew);
        }
        __syncwarp();
        unsigned old = 0u;
        if (lane == 0) old = atomicAdd(relcnt, 1u);
        old = __shfl_sync(0xffffffffu, old, 0);
        if (old == (unsigned)(W*t + W - 1)) {     // this warp is the CTA's last
            if (lane < NCTA)
                st_rel_rem(mapa_rank(flagbase + 4u*rank, lane), (unsigned)(t + 1));
        }
    }

    asm volatile("barrier.cluster.arrive.aligned;" ::: "memory");
    asm volatile("barrier.cluster.wait.aligned;" ::: "memory");
}

__global__ void __launch_bounds__(1024, 1) __cluster_dims__(8, 1, 1)
k_main8(const float* __restrict__ Wn, const float* __restrict__ Wg,
        const int* __restrict__ seq, const float* __restrict__ c0)
{ k_main_body<8>(Wn, Wg, seq, c0); }

__global__ void __launch_bounds__(512, 1)
k_main16(const float* __restrict__ Wn, const float* __restrict__ Wg,
         const int* __restrict__ seq, const float* __restrict__ c0)
{ k_main_body<16>(Wn, Wg, seq, c0); }

__global__ void __launch_bounds__(256) k_epi(const float* __restrict__ h0,
                                             float* __restrict__ out)
{
    for (int e = blockIdx.x*blockDim.x + threadIdx.x; e < NN*HH;
         e += gridDim.x*blockDim.x) {
        int node = e >> 8;
        int ls = __ldg(&d_lastStep[node]);
        float hval = (ls >= 0) ? d_hidver[ls*256 + (e & 255)] : __ldg(&h0[e]);
        out[e] = hval + __ldg(&h0[e]);
    }
}

extern "C" void kernel_launch(void* const* d_in, const int* in_sizes, int n_in,
                              void* d_out, int out_size) {
    const float* inputs  = (const float*)d_in[0];
    const float* nei     = (const float*)d_in[1];
    const float* numNei  = (const float*)d_in[2];
    const int*   seq     = (const int*)  d_in[3];
    const float* h0      = (const float*)d_in[4];
    const float* c0      = (const float*)d_in[5];
    const float* Wg      = (const float*)d_in[6];
    const float* bg      = (const float*)d_in[7];
    const float* Ws      = (const float*)d_in[8];
    const float* bs      = (const float*)d_in[9];
    const float* Wn      = (const float*)d_in[10];
    float* out = (float*)d_out;

    static int ncta_sel = 0;   // deterministic config choice, resolved once
    if (ncta_sel == 0) {
        cudaFuncSetAttribute(k_main8, cudaFuncAttributeMaxDynamicSharedMemorySize,
                             Cfg<8>::SMB);
        int ok16 = 0;
        if (cudaFuncSetAttribute(k_main16,
                cudaFuncAttributeNonPortableClusterSizeAllowed, 1) == cudaSuccess &&
            cudaFuncSetAttribute(k_main16,
                cudaFuncAttributeMaxDynamicSharedMemorySize, Cfg<16>::SMB) == cudaSuccess) {
            cudaLaunchConfig_t cfg = {};
            cfg.gridDim = dim3(16, 1, 1);
            cfg.blockDim = dim3(512, 1, 1);
            cfg.dynamicSmemBytes = Cfg<16>::SMB;
            cudaLaunchAttribute a[1];
            a[0].id = cudaLaunchAttributeClusterDimension;
            a[0].val.clusterDim = {16, 1, 1};
            cfg.attrs = a; cfg.numAttrs = 1;
            int num = 0;
            if (cudaOccupancyMaxActiveClusters(&num, k_main16, &cfg) == cudaSuccess
                && num >= 1)
                ok16 = 1;
        }
        cudaGetLastError();    // clear any probe error
        ncta_sel = ok16 ? 16 : 8;
    }

    k_init<<<16, 256>>>();
    k_pre1<<<SS, 256>>>(inputs, nei, numNei, seq, h0, Wg, bg, Ws, bs, Wn);
    k_pre2<<<dim3(SS/T_PER, NN/512), 256>>>(nei, seq);
    if (ncta_sel == 16) {
        cudaLaunchConfig_t cfg = {};
        cfg.gridDim = dim3(16, 1, 1);
        cfg.blockDim = dim3(512, 1, 1);
        cfg.dynamicSmemBytes = Cfg<16>::SMB;
        cudaLaunchAttribute a[1];
        a[0].id = cudaLaunchAttributeClusterDimension;
        a[0].val.clusterDim = {16, 1, 1};
        cfg.attrs = a; cfg.numAttrs = 1;
        cudaLaunchKernelEx(&cfg, k_main16, Wn, Wg, seq, c0);
    } else {
        k_main8<<<8, 1024, Cfg<8>::SMB>>>(Wn, Wg, seq, c0);
    }
    k_epi<<<148, 256>>>(h0, out);
}

// round 16
// speedup vs baseline: 2.3550x; 1.1250x over previous
#include <cuda_runtime.h>
#include <cstdint>

#define NN 4096
#define HH 256
#define SS 128
#define RPB1 32

// ---------------- persistent device scratch ----------------
__device__ __align__(16) float d_HW0[NN*HH];     // h0 @ Wn
__device__ __align__(16) float d_HG0[NN*HH];     // h0 @ Wg_bot
__device__ __align__(16) float d_FS[SS*HH];      // inp_t @ Ws + bs
__device__ __align__(16) float d_GI[SS*HH];      // inp_t @ Wg_top + bg
__device__ __align__(16) float d_NW0p[8][SS*HH]; // partial (nei_t @ h0) @ Wn
__device__ __align__(16) float d_S2p[8][SS*HH];  // partial S2base
__device__ __align__(16) float d_hidver[SS*HH];  // curHidden of step t
__device__ __align__(16) float d_pairWT[SS*SS];  // pairWT[t*SS+u] = nei[seq[t]][seq[u]]
__device__ float d_invN[SS];
__device__ int   d_lastVisit[SS];
__device__ int   d_lastStep[NN];

__device__ __forceinline__ float sig_t(float x) {   // sigmoid via tanh.approx (1 MUFU)
    float t;
    asm("tanh.approx.f32 %0, %1;" : "=f"(t) : "f"(0.5f * x));
    return fmaf(0.5f, t, 0.5f);
}
__device__ __forceinline__ float tanh_a(float x) {  // tanh.approx (1 MUFU)
    float t;
    asm("tanh.approx.f32 %0, %1;" : "=f"(t) : "f"(x));
    return t;
}

__global__ void k_init() {
    int e = blockIdx.x * blockDim.x + threadIdx.x;
    if (e < NN) d_lastStep[e] = -1;
}

__global__ void __launch_bounds__(256) k_pre1(
    const float* __restrict__ inputs, const float* __restrict__ nei,
    const float* __restrict__ numNei, const int* __restrict__ seq,
    const float* __restrict__ h0,
    const float* __restrict__ Wg, const float* __restrict__ bg,
    const float* __restrict__ Ws, const float* __restrict__ bs,
    const float* __restrict__ Wn)
{
    const int tid = threadIdx.x, b = blockIdx.x;
    __shared__ float sh[RPB1 * 256];

    const int r0 = b * RPB1;
    for (int e = tid; e < RPB1*256; e += 256) sh[e] = h0[(size_t)r0*256 + e];
    __syncthreads();
    {
        const int hq = (tid & 63) * 4;     // 4 h-columns per thread
        const int rg = (tid >> 6) * 8;     // 8 rows per thread
        float acc[8][4];
        #pragma unroll
        for (int r = 0; r < 8; ++r)
            #pragma unroll
            for (int c = 0; c < 4; ++c) acc[r][c] = 0.f;
        for (int k = 0; k < 256; ++k) {
            float4 wv = *(const float4*)&Wn[k*256 + hq];
            #pragma unroll
            for (int r = 0; r < 8; ++r) {
                float a = sh[(rg + r)*256 + k];
                acc[r][0] = fmaf(a, wv.x, acc[r][0]);
                acc[r][1] = fmaf(a, wv.y, acc[r][1]);
                acc[r][2] = fmaf(a, wv.z, acc[r][2]);
                acc[r][3] = fmaf(a, wv.w, acc[r][3]);
            }
        }
        #pragma unroll
        for (int r = 0; r < 8; ++r)
            *(float4*)&d_HW0[(size_t)(r0 + rg + r)*256 + hq] =
                make_float4(acc[r][0], acc[r][1], acc[r][2], acc[r][3]);
        #pragma unroll
        for (int r = 0; r < 8; ++r)
            #pragma unroll
            for (int c = 0; c < 4; ++c) acc[r][c] = 0.f;
        for (int k = 0; k < 256; ++k) {
            float4 wv = *(const float4*)&Wg[(256 + k)*256 + hq];
            #pragma unroll
            for (int r = 0; r < 8; ++r) {
                float a = sh[(rg + r)*256 + k];
                acc[r][0] = fmaf(a, wv.x, acc[r][0]);
                acc[r][1] = fmaf(a, wv.y, acc[r][1]);
                acc[r][2] = fmaf(a, wv.z, acc[r][2]);
                acc[r][3] = fmaf(a, wv.w, acc[r][3]);
            }
        }
        #pragma unroll
        for (int r = 0; r < 8; ++r)
            *(float4*)&d_HG0[(size_t)(r0 + rg + r)*256 + hq] =
                make_float4(acc[r][0], acc[r][1], acc[r][2], acc[r][3]);
    }
    __syncthreads();

    {   // b in [0, SS): FS/GI for step b + pairWT column
        int ii = __ldg(&seq[b]);
        for (int k = tid; k < 256; k += 256) sh[k] = inputs[(size_t)ii*256 + k];
        __syncthreads();
        const int h = tid;
        float fs = bs[h], gi = bg[h];
        for (int k = 0; k < 256; ++k) {
            float iv = sh[k];
            fs = fmaf(iv, __ldg(&Ws[k*256 + h]), fs);
            gi = fmaf(iv, __ldg(&Wg[k*256 + h]), gi);
        }
        d_FS[b*256 + h] = fs;
        d_GI[b*256 + h] = gi;
        if (tid < SS) {
            int tseq = __ldg(&seq[tid]);
            d_pairWT[tid*SS + b] = __ldg(&nei[(size_t)tseq*NN + ii]);
        }
    }

    if (b == 0 && tid < SS) {
        int me = __ldg(&seq[tid]);
        int lv = -1;
        for (int u = tid - 1; u >= 0; --u)
            if (__ldg(&seq[u]) == me) { lv = u; break; }
        d_lastVisit[tid] = lv;
        atomicMax(&d_lastStep[me], tid);
        d_invN[tid] = 1.0f / __ldg(&numNei[me]);
    }
}

// S2base / NW0 partials: 8 t's x 512 j's per block; grid (16, 8) = 128 blocks
#define T_PER 8
__global__ void __launch_bounds__(256) k_pre2(const float* __restrict__ nei,
                                              const int* __restrict__ seq)
{
    const int tid = threadIdx.x;
    const int tt0 = blockIdx.x * T_PER, j0 = blockIdx.y * 512, by = blockIdx.y;
    __shared__ float shw[T_PER][512];
    int sqs[T_PER];
    #pragma unroll
    for (int q = 0; q < T_PER; ++q) sqs[q] = __ldg(&seq[tt0 + q]);
    for (int e = tid; e < T_PER*512; e += 256) {
        int q = e >> 9, j = e & 511;
        shw[q][j] = __ldg(&nei[(size_t)sqs[q]*NN + j0 + j]);
    }
    __syncthreads();
    const int h = tid;
    float fs[T_PER], s1[T_PER], s2[T_PER];
    #pragma unroll
    for (int q = 0; q < T_PER; ++q) {
        fs[q] = __ldg(&d_FS[(tt0+q)*256 + h]); s1[q] = 0.f; s2[q] = 0.f;
    }
    #pragma unroll 2
    for (int j = 0; j < 512; ++j) {
        float hw = __ldg(&d_HW0[(size_t)(j0+j)*256 + h]);
        #pragma unroll
        for (int q = 0; q < T_PER; ++q) {
            float w = shw[q][j];
            s1[q] = fmaf(w, hw, s1[q]);
            s2[q] = fmaf(w, sig_t(fs[q] + hw), s2[q]);
        }
    }
    #pragma unroll
    for (int q = 0; q < T_PER; ++q) {
        d_NW0p[by][(tt0+q)*256 + h] = s1[q];
        d_S2p [by][(tt0+q)*256 + h] = s2[q];
    }
}

// ---------------- main serial loop (templated on cluster size) ----------------
template<int NCTA> struct Cfg {
    static constexpr int W    = 256 / NCTA;      // warps per CTA (1 per owned h)
    static constexpr int NT   = W * 32;
    static constexpr int O_WN   = 0;             // [W][256]
    static constexpr int O_PW   = O_WN + W*256;  // [SS][SS]
    static constexpr int O_FS   = O_PW + SS*SS;  // [SS][W]
    static constexpr int O_GIPN = O_FS + SS*W;
    static constexpr int O_S2N  = O_GIPN + SS*W;
    static constexpr int O_C0   = O_S2N + SS*W;
    static constexpr int O_HW0G = O_C0 + SS*W;
    static constexpr int O_HG0G = O_HW0G + SS*W;
    static constexpr int O_CELL = O_HG0G + SS*W;
    static constexpr int O_INV  = O_CELL + SS*W; // [SS]
    static constexpr int O_HIDB = O_INV + SS;    // [2][256]
    static constexpr int O_END  = O_HIDB + 2*HH;
    static constexpr int FLAG_BYTE = ((O_END*4 + SS*4) + 15) & ~15;
    static constexpr int SMB = FLAG_BYTE + 128;
};

__device__ __forceinline__ uint32_t smem_u32(const void* p) {
    uint32_t a;
    asm("{ .reg .u64 t; cvta.to.shared.u64 t, %1; cvt.u32.u64 %0, t; }"
        : "=r"(a) : "l"(p));
    return a;
}
__device__ __forceinline__ uint32_t mapa_rank(uint32_t addr, int rank) {
    uint32_t r;
    asm("mapa.shared::cluster.u32 %0, %1, %2;" : "=r"(r) : "r"(addr), "r"(rank));
    return r;
}
__device__ __forceinline__ unsigned ld_acq_sh(uint32_t addr) {
    unsigned v;
    asm volatile("ld.acquire.cluster.shared::cta.b32 %0, [%1];"
                 : "=r"(v) : "r"(addr) : "memory");
    return v;
}
__device__ __forceinline__ void st_rlx_rem(uint32_t addr, float v) {
    asm volatile("st.relaxed.cluster.shared::cluster.b32 [%0], %1;"
                 :: "r"(addr), "r"(__float_as_uint(v)) : "memory");
}
__device__ __forceinline__ void st_rel_rem(uint32_t addr, unsigned v) {
    asm volatile("st.release.cluster.shared::cluster.b32 [%0], %1;"
                 :: "r"(addr), "r"(v) : "memory");
}

template<int NCTA>
__device__ __forceinline__ void k_main_body(
    const float* __restrict__ Wn, const float* __restrict__ Wg,
    const int* __restrict__ seq, const float* __restrict__ c0)
{
    using C = Cfg<NCTA>;
    constexpr int W = C::W;
    extern __shared__ __align__(16) float sm[];
    int* sslv = (int*)(sm + C::O_END);
    const uint32_t smbase = smem_u32(sm);
    const uint32_t flagbase = smbase + C::FLAG_BYTE;

    const int tid  = threadIdx.x;
    const int wid  = tid >> 5;
    const int lane = tid & 31;
    const int rank = blockIdx.x;
    const int h_base = rank * W;
    const int h = h_base + wid;

    // -------- preamble --------
    for (int k = lane; k < 256; k += 32)
        sm[C::O_WN + wid*256 + k] = __ldg(&Wn[k*256 + h]);
    for (int e = tid; e < SS*SS; e += C::NT)
        sm[C::O_PW + e] = d_pairWT[e];
    for (int e = tid; e < SS*W; e += C::NT) {
        int t = e / W, hl = e % W;
        int hcol = h_base + hl;
        int node = __ldg(&seq[t]);
        float invn = d_invN[t];
        float nv = 0.f, s2v = 0.f;
        #pragma unroll
        for (int p = 0; p < 8; ++p) {
            nv  += d_NW0p[p][t*256 + hcol];
            s2v += d_S2p [p][t*256 + hcol];
        }
        sm[C::O_FS   + e] = d_FS[t*256 + hcol];
        sm[C::O_GIPN + e] = d_GI[t*256 + hcol] + nv * invn;
        sm[C::O_S2N  + e] = s2v * invn;
        sm[C::O_C0   + e] = __ldg(&c0[(size_t)node*256 + hcol]);
        sm[C::O_HW0G + e] = d_HW0[(size_t)node*256 + hcol];
        sm[C::O_HG0G + e] = d_HG0[(size_t)node*256 + hcol];
    }
    if (tid < SS) {
        sslv[tid] = d_lastVisit[tid];
        sm[C::O_INV + tid] = d_invN[tid];
    }
    if (tid < NCTA) ((unsigned*)(sm + (C::FLAG_BYTE/4)))[tid] = 0u;
    __syncthreads();
    asm volatile("barrier.cluster.arrive.aligned;" ::: "memory");
    asm volatile("barrier.cluster.wait.aligned;" ::: "memory");

    // per-lane visit-slot caches: slot u = lane + 32*q
    float hv0=0.f,hv1=0.f,hv2=0.f,hv3=0.f;
    float hb0=0.f,hb1=0.f,hb2=0.f,hb3=0.f;

    for (int t = 0; t < SS; ++t) {
        const int lv = sslv[t];
        const float fsv = sm[C::O_FS + t*W + wid];
        const int pb = (t - 1) & 1;
        const float* pw = sm + C::O_PW + t*SS;

        // ===== pre-wait (overlaps previous step's communication) =====
        float s1p = 0.f, s2p = 0.f;
        const int lim = t - 2;
        if (lane <= lim) {
            float w = pw[lane];
            s1p = fmaf(w, hv0 - hb0, s1p);
            s2p = fmaf(w, sig_t(fsv + hv0) - sig_t(fsv + hb0), s2p);
        }
        if (lane + 32 <= lim) {
            float w = pw[lane + 32];
            s1p = fmaf(w, hv1 - hb1, s1p);
            s2p = fmaf(w, sig_t(fsv + hv1) - sig_t(fsv + hb1), s2p);
        }
        if (lane + 64 <= lim) {
            float w = pw[lane + 64];
            s1p = fmaf(w, hv2 - hb2, s1p);
            s2p = fmaf(w, sig_t(fsv + hv2) - sig_t(fsv + hb2), s2p);
        }
        if (lane + 96 <= lim) {
            float w = pw[lane + 96];
            s1p = fmaf(w, hv3 - hb3, s1p);
            s2p = fmaf(w, sig_t(fsv + hv3) - sig_t(fsv + hb3), s2p);
        }
        #pragma unroll
        for (int o = 16; o; o >>= 1) {          // full reduce pre-wait
            s1p += __shfl_xor_sync(0xffffffffu, s1p, o);
            s2p += __shfl_xor_sync(0xffffffffu, s2p, o);
        }

        // revisit prep (lv <= t-2)
        float hv_sel = 0.f, hgdyn = 0.f;
        const bool lv_old = (lv >= 0) && (lv < t - 1);
        if (lv_old) {
            int q = lv >> 5;
            float s = (q == 0) ? hv0 : (q == 1) ? hv1 : (q == 2) ? hv2 : hv3;
            hv_sel = __shfl_sync(0xffffffffu, s, lv & 31);
            const float* hvp = d_hidver + lv*256;
            #pragma unroll
            for (int qq = 0; qq < 8; ++qq) {
                int k = lane + 32*qq;
                hgdyn += __ldcg(&hvp[k]) * __ldg(&Wg[(256 + k)*256 + h]);
            }
            #pragma unroll
            for (int o = 16; o; o >>= 1)
                hgdyn += __shfl_xor_sync(0xffffffffu, hgdyn, o);
        }
        float HWi_e = lv_old ? hv_sel : sm[C::O_HW0G + t*W + wid];
        float fS_e = 0.f;
        if (lane == 0 && lv != t - 1) fS_e = sig_t(fsv + HWi_e);

        // ===== per-warp wait for hid[t-1] packet =====
        if (t > 0) {
            unsigned ok;
            do {
                unsigned f = (lane < NCTA) ? ld_acq_sh(flagbase + 4u*lane) : 0u;
                ok = __all_sync(0xffffffffu,
                                (lane < NCTA) ? (f >= (unsigned)t) : 1u);
            } while (!ok);
        }

        // ===== post-wait: dot + slot-(t-1) correction =====
        float hwnew = 0.f, c1 = 0.f, c2 = 0.f;
        if (t > 0) {
            const float4* hv4 = (const float4*)(sm + C::O_HIDB + pb*HH);
            const float4* wn4 = (const float4*)(sm + C::O_WN + wid*256);
            float4 x0 = hv4[lane*2],   a0 = wn4[lane*2];
            float4 x1 = hv4[lane*2+1], a1 = wn4[lane*2+1];
            hwnew = x0.x*a0.x + x0.y*a0.y + x0.z*a0.z + x0.w*a0.w
                  + x1.x*a1.x + x1.y*a1.y + x1.z*a1.z + x1.w*a1.w;
            #pragma unroll
            for (int o = 16; o; o >>= 1)
                hwnew += __shfl_xor_sync(0xffffffffu, hwnew, o);
            const int slot = t - 1, owner = slot & 31, q = slot >> 5;
            if (lane == owner) {
                float hbp;
                if (q == 0)      { hbp = hb0; hv0 = hwnew; }
                else if (q == 1) { hbp = hb1; hv1 = hwnew; }
                else if (q == 2) { hbp = hb2; hv2 = hwnew; }
                else             { hbp = hb3; hv3 = hwnew; }
                float w = pw[slot];
                c1 = w * (hwnew - hbp);
                c2 = w * (sig_t(fsv + hwnew) - sig_t(fsv + hbp));
            }
            c1 = __shfl_sync(0xffffffffu, c1, owner);
            c2 = __shfl_sync(0xffffffffu, c2, owner);
        }

        // rare: revisit of immediately preceding step
        if (lv == t - 1 && t > 0) {
            const float* hvp = sm + C::O_HIDB + pb*HH;
            float g = 0.f;
            #pragma unroll
            for (int qq = 0; qq < 8; ++qq) {
                int k = lane + 32*qq;
                g += hvp[k] * __ldg(&Wg[(256 + k)*256 + h]);
            }
            #pragma unroll
            for (int o = 16; o; o >>= 1)
                g += __shfl_xor_sync(0xffffffffu, g, o);
            hgdyn = g;
            hv_sel = hwnew;
        }

        // ===== gates (lane 0), MUFU via tanh.approx =====
        float hid_l0 = 0.f, HWi_l0 = 0.f;
        if (lane == 0) {
            const int eb = t*W + wid;
            float HWi, HGi, cprev, fS;
            if (lv >= 0) { HWi = hv_sel; HGi = hgdyn;
                           cprev = sm[C::O_CELL + lv*W + wid]; }
            else         { HWi = HWi_e; HGi = sm[C::O_HG0G + eb];
                           cprev = sm[C::O_C0 + eb]; }
            fS = (lv == t - 1) ? sig_t(fsv + HWi) : fS_e;
            float invn = sm[C::O_INV + t];
            float pre  = sm[C::O_GIPN + eb] + HGi + (s1p + c1) * invn;
            float S2n  = sm[C::O_S2N + eb] + (s2p + c2) * invn;
            float iS   = sig_t(pre);
            float hC   = tanh_a(pre);
            float cC   = fmaf(S2n, cprev, fmaf(fS, cprev, iS*hC));
            sm[C::O_CELL + eb] = cC;
            hid_l0 = tanh_a(iS * cC);
            __stcg(&d_hidver[t*256 + h], hid_l0);
            HWi_l0 = HWi;
        }
        float hidnew  = __shfl_sync(0xffffffffu, hid_l0, 0);
        float HWi_all = __shfl_sync(0xffffffffu, HWi_l0, 0);
        if (lane == (t & 31)) {
            int q = t >> 5;
            if (q == 0) hb0 = HWi_all; else if (q == 1) hb1 = HWi_all;
            else if (q == 2) hb2 = HWi_all; else hb3 = HWi_all;
        }

        // ===== push to all NCTA CTAs; warp0 releases flags after bar =====
        if (lane < NCTA) {
            uint32_t loc = smbase + (uint32_t)(C::O_HIDB + (t & 1)*HH + h) * 4u;
            st_rlx_rem(mapa_rank(loc, lane), hidnew);
        }
        if (wid == 0) {
            asm volatile("bar.sync 1, %0;" :: "r"(C::NT) : "memory");
            if (lane < NCTA)
                st_rel_rem(mapa_rank(flagbase + 4u*rank, lane), (unsigned)(t + 1));
        } else {
            asm volatile("bar.arrive 1, %0;" :: "r"(C::NT) : "memory");
        }
    }

    asm volatile("barrier.cluster.arrive.aligned;" ::: "memory");
    asm volatile("barrier.cluster.wait.aligned;" ::: "memory");
}

__global__ void __launch_bounds__(1024, 1) __cluster_dims__(8, 1, 1)
k_main8(const float* __restrict__ Wn, const float* __restrict__ Wg,
        const int* __restrict__ seq, const float* __restrict__ c0)
{ k_main_body<8>(Wn, Wg, seq, c0); }

__global__ void __launch_bounds__(512, 1)
k_main16(const float* __restrict__ Wn, const float* __restrict__ Wg,
         const int* __restrict__ seq, const float* __restrict__ c0)
{ k_main_body<16>(Wn, Wg, seq, c0); }

__global__ void __launch_bounds__(256) k_epi(const float* __restrict__ h0,
                                             float* __restrict__ out)
{
    for (int e = blockIdx.x*blockDim.x + threadIdx.x; e < NN*HH;
         e += gridDim.x*blockDim.x) {
        int node = e >> 8;
        int ls = __ldg(&d_lastStep[node]);
        float hval = (ls >= 0) ? d_hidver[ls*256 + (e & 255)] : __ldg(&h0[e]);
        out[e] = hval + __ldg(&h0[e]);
    }
}

extern "C" void kernel_launch(void* const* d_in, const int* in_sizes, int n_in,
                              void* d_out, int out_size) {
    const float* inputs  = (const float*)d_in[0];
    const float* nei     = (const float*)d_in[1];
    const float* numNei  = (const float*)d_in[2];
    const int*   seq     = (const int*)  d_in[3];
    const float* h0      = (const float*)d_in[4];
    const float* c0      = (const float*)d_in[5];
    const float* Wg      = (const float*)d_in[6];
    const float* bg      = (const float*)d_in[7];
    const float* Ws      = (const float*)d_in[8];
    const float* bs      = (const float*)d_in[9];
    const float* Wn      = (const float*)d_in[10];
    float* out = (float*)d_out;

    static int ncta_sel = 0;   // deterministic config choice, resolved once
    if (ncta_sel == 0) {
        cudaFuncSetAttribute(k_main8, cudaFuncAttributeMaxDynamicSharedMemorySize,
                             Cfg<8>::SMB);
        int ok16 = 0;
        if (cudaFuncSetAttribute(k_main16,
                cudaFuncAttributeNonPortableClusterSizeAllowed, 1) == cudaSuccess &&
            cudaFuncSetAttribute(k_main16,
                cudaFuncAttributeMaxDynamicSharedMemorySize, Cfg<16>::SMB) == cudaSuccess) {
            cudaLaunchConfig_t cfg = {};
            cfg.gridDim = dim3(16, 1, 1);
            cfg.blockDim = dim3(512, 1, 1);
            cfg.dynamicSmemBytes = Cfg<16>::SMB;
            cudaLaunchAttribute a[1];
            a[0].id = cudaLaunchAttributeClusterDimension;
            a[0].val.clusterDim = {16, 1, 1};
            cfg.attrs = a; cfg.numAttrs = 1;
            int num = 0;
            if (cudaOccupancyMaxActiveClusters(&num, k_main16, &cfg) == cudaSuccess
                && num >= 1)
                ok16 = 1;
        }
        cudaGetLastError();    // clear any probe error
        ncta_sel = ok16 ? 16 : 8;
    }

    k_init<<<16, 256>>>();
    k_pre1<<<SS, 256>>>(inputs, nei, numNei, seq, h0, Wg, bg, Ws, bs, Wn);
    k_pre2<<<dim3(SS/T_PER, NN/512), 256>>>(nei, seq);
    if (ncta_sel == 16) {
        cudaLaunchConfig_t cfg = {};
        cfg.gridDim = dim3(16, 1, 1);
        cfg.blockDim = dim3(512, 1, 1);
        cfg.dynamicSmemBytes = Cfg<16>::SMB;
        cudaLaunchAttribute a[1];
        a[0].id = cudaLaunchAttributeClusterDimension;
        a[0].val.clusterDim = {16, 1, 1};
        cfg.attrs = a; cfg.numAttrs = 1;
        cudaLaunchKernelEx(&cfg, k_main16, Wn, Wg, seq, c0);
    } else {
        k_main8<<<8, 1024, Cfg<8>::SMB>>>(Wn, Wg, seq, c0);
    }
    k_epi<<<148, 256>>>(h0, out);
}